// round 1
// baseline (speedup 1.0000x reference)
#include <cuda_runtime.h>

// Problem constants
#define BB   2
#define SS   2048
#define DIM  1024
#define HH   16
#define DD   64

// Scratch (device globals — allocation-free rule)
__device__ float g_Q[BB*HH*SS*DD];   // [B,H,S,D] 16MB
__device__ float g_K[BB*HH*SS*DD];
__device__ float g_V[BB*HH*SS*DD];
__device__ float g_C[BB*SS*DIM];     // concat [B,S,DIM]

// ---------------------------------------------------------------------------
// Generic 64x64 tile SGEMM: C = A[MxK] @ W[KxN] + bias[N]
// split=1: scatter output into head-split layout [B,H,S,D]
// 256 threads, each computes a 4x4 micro-tile. BK=16.
// ---------------------------------------------------------------------------
__global__ void sgemm_bias_kernel(const float* __restrict__ A,
                                  const float* __restrict__ W,
                                  const float* __restrict__ bias,
                                  float* __restrict__ Cout,
                                  int M, int N, int K, int split)
{
    __shared__ float As[16][64];
    __shared__ float Ws[16][64];

    const int tid = threadIdx.x;
    const int tx  = tid & 15;
    const int ty  = tid >> 4;
    const int m0  = blockIdx.y * 64;
    const int n0  = blockIdx.x * 64;

    const int arow = tid >> 2, akq = tid & 3;   // A tile loader mapping
    const int wrow = tid >> 4, wnq = tid & 15;  // W tile loader mapping

    float acc[4][4] = {};

    for (int k0 = 0; k0 < K; k0 += 16) {
        float4 a4 = *(const float4*)&A[(size_t)(m0 + arow) * K + k0 + akq * 4];
        float4 w4 = *(const float4*)&W[(size_t)(k0 + wrow) * N + n0 + wnq * 4];
        As[akq*4+0][arow] = a4.x;
        As[akq*4+1][arow] = a4.y;
        As[akq*4+2][arow] = a4.z;
        As[akq*4+3][arow] = a4.w;
        *(float4*)&Ws[wrow][wnq*4] = w4;
        __syncthreads();
#pragma unroll
        for (int k = 0; k < 16; k++) {
            float4 a = *(float4*)&As[k][ty*4];
            float4 w = *(float4*)&Ws[k][tx*4];
            float av[4] = {a.x, a.y, a.z, a.w};
            float wv[4] = {w.x, w.y, w.z, w.w};
#pragma unroll
            for (int i = 0; i < 4; i++)
#pragma unroll
                for (int j = 0; j < 4; j++)
                    acc[i][j] += av[i] * wv[j];
        }
        __syncthreads();
    }

#pragma unroll
    for (int i = 0; i < 4; i++) {
#pragma unroll
        for (int j = 0; j < 4; j++) {
            int m = m0 + ty*4 + i;
            int n = n0 + tx*4 + j;
            float v = acc[i][j] + bias[n];
            if (split) {
                int b = m >> 11, s = m & 2047;   // S=2048
                int h = n >> 6,  d = n & 63;     // D=64
                g_dummy:
                Cout[(((size_t)(b*HH + h) * SS) + s) * DD + d] = v;
            } else {
                Cout[(size_t)m * N + n] = v;
            }
        }
    }
}

// ---------------------------------------------------------------------------
// Logits: for each (b,h): L[t,s] = (Q_h[t,:]·K_h[s,:]) * 1/8 + bias[b,h,t,s]
//         + (-1e9)*(1 - mask)
// grid: (S/64 over s, S/64 over t, B*H). K-dim = 64 (4 x BK=16).
// ---------------------------------------------------------------------------
__global__ void logits_kernel(const float* __restrict__ Q,
                              const float* __restrict__ Km,
                              const float* __restrict__ bias4d,
                              const float* __restrict__ paddings,
                              float* __restrict__ attn)
{
    __shared__ float Qs[16][64];
    __shared__ float Ks[16][64];

    const int tid = threadIdx.x;
    const int tx  = tid & 15;
    const int ty  = tid >> 4;
    const int bh  = blockIdx.z;
    const int b   = bh >> 4;
    const int t0  = blockIdx.y * 64;
    const int s0  = blockIdx.x * 64;

    const float* Qh = Q  + (size_t)bh * SS * DD;
    const float* Kh = Km + (size_t)bh * SS * DD;

    const int row = tid >> 2, kq = tid & 3;

    float acc[4][4] = {};

    for (int k0 = 0; k0 < 64; k0 += 16) {
        float4 q4 = *(const float4*)&Qh[(size_t)(t0 + row) * DD + k0 + kq*4];
        float4 k4 = *(const float4*)&Kh[(size_t)(s0 + row) * DD + k0 + kq*4];
        Qs[kq*4+0][row] = q4.x; Qs[kq*4+1][row] = q4.y;
        Qs[kq*4+2][row] = q4.z; Qs[kq*4+3][row] = q4.w;
        Ks[kq*4+0][row] = k4.x; Ks[kq*4+1][row] = k4.y;
        Ks[kq*4+2][row] = k4.z; Ks[kq*4+3][row] = k4.w;
        __syncthreads();
#pragma unroll
        for (int k = 0; k < 16; k++) {
            float4 a = *(float4*)&Qs[k][ty*4];
            float4 w = *(float4*)&Ks[k][tx*4];
            float av[4] = {a.x, a.y, a.z, a.w};
            float wv[4] = {w.x, w.y, w.z, w.w};
#pragma unroll
            for (int i = 0; i < 4; i++)
#pragma unroll
                for (int j = 0; j < 4; j++)
                    acc[i][j] += av[i] * wv[j];
        }
        __syncthreads();
    }

#pragma unroll
    for (int i = 0; i < 4; i++) {
        int t = t0 + ty*4 + i;
        float mt = 1.0f - paddings[b * SS + t];
#pragma unroll
        for (int j = 0; j < 4; j++) {
            int s = s0 + tx*4 + j;
            float ms = 1.0f - paddings[b * SS + s];
            float v = acc[i][j] * 0.125f
                    + bias4d[((size_t)bh * SS + t) * SS + s]
                    + (-1e9f) * (1.0f - mt * ms);
            attn[((size_t)bh * SS + t) * SS + s] = v;
        }
    }
}

// ---------------------------------------------------------------------------
// Row softmax, in-place. One block (256 threads) per row of 2048.
// ---------------------------------------------------------------------------
__global__ void softmax_kernel(float* __restrict__ attn)
{
    __shared__ float sred[8];
    const int tid = threadIdx.x;
    float* p = attn + (size_t)blockIdx.x * SS;

    float4 v0 = *(float4*)&p[tid * 4];
    float4 v1 = *(float4*)&p[1024 + tid * 4];

    // max
    float m = fmaxf(fmaxf(fmaxf(v0.x, v0.y), fmaxf(v0.z, v0.w)),
                    fmaxf(fmaxf(v1.x, v1.y), fmaxf(v1.z, v1.w)));
#pragma unroll
    for (int o = 16; o; o >>= 1) m = fmaxf(m, __shfl_xor_sync(~0u, m, o));
    if ((tid & 31) == 0) sred[tid >> 5] = m;
    __syncthreads();
    if (tid == 0) {
        float t = sred[0];
#pragma unroll
        for (int i = 1; i < 8; i++) t = fmaxf(t, sred[i]);
        sred[0] = t;
    }
    __syncthreads();
    m = sred[0];
    __syncthreads();

    // exp + sum
    v0.x = expf(v0.x - m); v0.y = expf(v0.y - m);
    v0.z = expf(v0.z - m); v0.w = expf(v0.w - m);
    v1.x = expf(v1.x - m); v1.y = expf(v1.y - m);
    v1.z = expf(v1.z - m); v1.w = expf(v1.w - m);
    float s = v0.x + v0.y + v0.z + v0.w + v1.x + v1.y + v1.z + v1.w;
#pragma unroll
    for (int o = 16; o; o >>= 1) s += __shfl_xor_sync(~0u, s, o);
    if ((tid & 31) == 0) sred[tid >> 5] = s;
    __syncthreads();
    if (tid == 0) {
        float t = 0.f;
#pragma unroll
        for (int i = 0; i < 8; i++) t += sred[i];
        sred[0] = t;
    }
    __syncthreads();
    float inv = 1.0f / sred[0];

    v0.x *= inv; v0.y *= inv; v0.z *= inv; v0.w *= inv;
    v1.x *= inv; v1.y *= inv; v1.z *= inv; v1.w *= inv;
    *(float4*)&p[tid * 4]        = v0;
    *(float4*)&p[1024 + tid * 4] = v1;
}

// ---------------------------------------------------------------------------
// AV: per (b,h): O[t,d] = sum_s Wgt[t,s] * V_h[s,d]; write into concat layout.
// grid: (S/64 over t, B*H). 64x64 output tile (full D=64). BK=16, K=2048.
// ---------------------------------------------------------------------------
__global__ void av_kernel(const float* __restrict__ attn,
                          const float* __restrict__ V,
                          float* __restrict__ concat)
{
    __shared__ float Wsm[16][64];
    __shared__ float Vs[16][64];

    const int tid = threadIdx.x;
    const int tx  = tid & 15;
    const int ty  = tid >> 4;
    const int t0  = blockIdx.x * 64;
    const int bh  = blockIdx.y;
    const int b   = bh >> 4;
    const int h   = bh & 15;

    const float* Ah = attn + (size_t)bh * SS * SS;
    const float* Vh = V    + (size_t)bh * SS * DD;

    const int arow = tid >> 2, akq = tid & 3;   // weights tile
    const int vrow = tid >> 4, vdq = tid & 15;  // V tile

    float acc[4][4] = {};

    for (int k0 = 0; k0 < SS; k0 += 16) {
        float4 a4 = *(const float4*)&Ah[(size_t)(t0 + arow) * SS + k0 + akq*4];
        float4 v4 = *(const float4*)&Vh[(size_t)(k0 + vrow) * DD + vdq*4];
        Wsm[akq*4+0][arow] = a4.x;
        Wsm[akq*4+1][arow] = a4.y;
        Wsm[akq*4+2][arow] = a4.z;
        Wsm[akq*4+3][arow] = a4.w;
        *(float4*)&Vs[vrow][vdq*4] = v4;
        __syncthreads();
#pragma unroll
        for (int k = 0; k < 16; k++) {
            float4 a = *(float4*)&Wsm[k][ty*4];
            float4 w = *(float4*)&Vs[k][tx*4];
            float av[4] = {a.x, a.y, a.z, a.w};
            float wv[4] = {w.x, w.y, w.z, w.w};
#pragma unroll
            for (int i = 0; i < 4; i++)
#pragma unroll
                for (int j = 0; j < 4; j++)
                    acc[i][j] += av[i] * wv[j];
        }
        __syncthreads();
    }

#pragma unroll
    for (int i = 0; i < 4; i++) {
        int t = t0 + ty*4 + i;
#pragma unroll
        for (int j = 0; j < 4; j++) {
            int d = tx*4 + j;
            concat[((size_t)(b * SS + t)) * DIM + h * DD + d] = acc[i][j];
        }
    }
}

// ---------------------------------------------------------------------------
extern "C" void kernel_launch(void* const* d_in, const int* in_sizes, int n_in,
                              void* d_out, int out_size)
{
    const float* query    = (const float*)d_in[0];
    const float* key      = (const float*)d_in[1];
    const float* value    = (const float*)d_in[2];
    const float* attnbias = (const float*)d_in[3];
    const float* paddings = (const float*)d_in[4];
    const float* wq_w = (const float*)d_in[5];
    const float* wq_b = (const float*)d_in[6];
    const float* wk_w = (const float*)d_in[7];
    const float* wk_b = (const float*)d_in[8];
    const float* wv_w = (const float*)d_in[9];
    const float* wv_b = (const float*)d_in[10];
    const float* wo_w = (const float*)d_in[11];
    const float* wo_b = (const float*)d_in[12];

    float* out  = (float*)d_out;                       // [B,S,DIM]
    float* attn = out + (size_t)BB * SS * DIM;         // [B,H,S,S] attention weights

    float *Qp, *Kp, *Vp, *Cp;
    cudaGetSymbolAddress((void**)&Qp, g_Q);
    cudaGetSymbolAddress((void**)&Kp, g_K);
    cudaGetSymbolAddress((void**)&Vp, g_V);
    cudaGetSymbolAddress((void**)&Cp, g_C);

    dim3 blk(256);
    dim3 gproj(DIM / 64, (BB * SS) / 64);   // (16, 64)

    // QKV projections (head-split outputs)
    sgemm_bias_kernel<<<gproj, blk>>>(query, wq_w, wq_b, Qp, BB*SS, DIM, DIM, 1);
    sgemm_bias_kernel<<<gproj, blk>>>(key,   wk_w, wk_b, Kp, BB*SS, DIM, DIM, 1);
    sgemm_bias_kernel<<<gproj, blk>>>(value, wv_w, wv_b, Vp, BB*SS, DIM, DIM, 1);

    // Logits + bias + mask -> attn region of d_out
    dim3 glog(SS / 64, SS / 64, BB * HH);   // (32, 32, 32)
    logits_kernel<<<glog, blk>>>(Qp, Kp, attnbias, paddings, attn);

    // Row softmax in-place
    softmax_kernel<<<BB * HH * SS, 256>>>(attn);

    // AV -> concat
    dim3 gav(SS / 64, BB * HH);             // (32, 32)
    av_kernel<<<gav, blk>>>(attn, Vp, Cp);

    // Output projection -> out
    sgemm_bias_kernel<<<gproj, blk>>>(Cp, wo_w, wo_b, out, BB*SS, DIM, DIM, 0);
}

// round 2
// speedup vs baseline: 1.0051x; 1.0051x over previous
#include <cuda_runtime.h>

// Problem constants
#define BB   2
#define SS   2048
#define DIM  1024
#define HH   16
#define DD   64

// Scratch (device globals — allocation-free rule)
__device__ float g_Q[BB*HH*SS*DD];   // [B,H,S,D] 16MB
__device__ float g_K[BB*HH*SS*DD];
__device__ float g_V[BB*HH*SS*DD];
__device__ float g_C[BB*SS*DIM];     // concat [B,S,DIM]

// ---------------------------------------------------------------------------
// Generic 64x64 tile SGEMM: C = A[MxK] @ W[KxN] + bias[N]
// split=1: scatter output into head-split layout [B,H,S,D]
// 256 threads, each computes a 4x4 micro-tile. BK=16.
// ---------------------------------------------------------------------------
__global__ void sgemm_bias_kernel(const float* __restrict__ A,
                                  const float* __restrict__ W,
                                  const float* __restrict__ bias,
                                  float* __restrict__ Cout,
                                  int M, int N, int K, int split)
{
    __shared__ float As[16][64];
    __shared__ float Ws[16][64];

    const int tid = threadIdx.x;
    const int tx  = tid & 15;
    const int ty  = tid >> 4;
    const int m0  = blockIdx.y * 64;
    const int n0  = blockIdx.x * 64;

    const int arow = tid >> 2, akq = tid & 3;   // A tile loader mapping
    const int wrow = tid >> 4, wnq = tid & 15;  // W tile loader mapping

    float acc[4][4] = {};

    for (int k0 = 0; k0 < K; k0 += 16) {
        float4 a4 = *(const float4*)&A[(size_t)(m0 + arow) * K + k0 + akq * 4];
        float4 w4 = *(const float4*)&W[(size_t)(k0 + wrow) * N + n0 + wnq * 4];
        As[akq*4+0][arow] = a4.x;
        As[akq*4+1][arow] = a4.y;
        As[akq*4+2][arow] = a4.z;
        As[akq*4+3][arow] = a4.w;
        *(float4*)&Ws[wrow][wnq*4] = w4;
        __syncthreads();
#pragma unroll
        for (int k = 0; k < 16; k++) {
            float4 a = *(float4*)&As[k][ty*4];
            float4 w = *(float4*)&Ws[k][tx*4];
            float av[4] = {a.x, a.y, a.z, a.w};
            float wv[4] = {w.x, w.y, w.z, w.w};
#pragma unroll
            for (int i = 0; i < 4; i++)
#pragma unroll
                for (int j = 0; j < 4; j++)
                    acc[i][j] += av[i] * wv[j];
        }
        __syncthreads();
    }

#pragma unroll
    for (int i = 0; i < 4; i++) {
#pragma unroll
        for (int j = 0; j < 4; j++) {
            int m = m0 + ty*4 + i;
            int n = n0 + tx*4 + j;
            float v = acc[i][j] + bias[n];
            if (split) {
                int b = m >> 11, s = m & 2047;   // S=2048
                int h = n >> 6,  d = n & 63;     // D=64
                g_dummy:
                Cout[(((size_t)(b*HH + h) * SS) + s) * DD + d] = v;
            } else {
                Cout[(size_t)m * N + n] = v;
            }
        }
    }
}

// ---------------------------------------------------------------------------
// Logits: for each (b,h): L[t,s] = (Q_h[t,:]·K_h[s,:]) * 1/8 + bias[b,h,t,s]
//         + (-1e9)*(1 - mask)
// grid: (S/64 over s, S/64 over t, B*H). K-dim = 64 (4 x BK=16).
// ---------------------------------------------------------------------------
__global__ void logits_kernel(const float* __restrict__ Q,
                              const float* __restrict__ Km,
                              const float* __restrict__ bias4d,
                              const float* __restrict__ paddings,
                              float* __restrict__ attn)
{
    __shared__ float Qs[16][64];
    __shared__ float Ks[16][64];

    const int tid = threadIdx.x;
    const int tx  = tid & 15;
    const int ty  = tid >> 4;
    const int bh  = blockIdx.z;
    const int b   = bh >> 4;
    const int t0  = blockIdx.y * 64;
    const int s0  = blockIdx.x * 64;

    const float* Qh = Q  + (size_t)bh * SS * DD;
    const float* Kh = Km + (size_t)bh * SS * DD;

    const int row = tid >> 2, kq = tid & 3;

    float acc[4][4] = {};

    for (int k0 = 0; k0 < 64; k0 += 16) {
        float4 q4 = *(const float4*)&Qh[(size_t)(t0 + row) * DD + k0 + kq*4];
        float4 k4 = *(const float4*)&Kh[(size_t)(s0 + row) * DD + k0 + kq*4];
        Qs[kq*4+0][row] = q4.x; Qs[kq*4+1][row] = q4.y;
        Qs[kq*4+2][row] = q4.z; Qs[kq*4+3][row] = q4.w;
        Ks[kq*4+0][row] = k4.x; Ks[kq*4+1][row] = k4.y;
        Ks[kq*4+2][row] = k4.z; Ks[kq*4+3][row] = k4.w;
        __syncthreads();
#pragma unroll
        for (int k = 0; k < 16; k++) {
            float4 a = *(float4*)&Qs[k][ty*4];
            float4 w = *(float4*)&Ks[k][tx*4];
            float av[4] = {a.x, a.y, a.z, a.w};
            float wv[4] = {w.x, w.y, w.z, w.w};
#pragma unroll
            for (int i = 0; i < 4; i++)
#pragma unroll
                for (int j = 0; j < 4; j++)
                    acc[i][j] += av[i] * wv[j];
        }
        __syncthreads();
    }

#pragma unroll
    for (int i = 0; i < 4; i++) {
        int t = t0 + ty*4 + i;
        float mt = 1.0f - paddings[b * SS + t];
#pragma unroll
        for (int j = 0; j < 4; j++) {
            int s = s0 + tx*4 + j;
            float ms = 1.0f - paddings[b * SS + s];
            float v = acc[i][j] * 0.125f
                    + bias4d[((size_t)bh * SS + t) * SS + s]
                    + (-1e9f) * (1.0f - mt * ms);
            attn[((size_t)bh * SS + t) * SS + s] = v;
        }
    }
}

// ---------------------------------------------------------------------------
// Row softmax, in-place. One block (256 threads) per row of 2048.
// ---------------------------------------------------------------------------
__global__ void softmax_kernel(float* __restrict__ attn)
{
    __shared__ float sred[8];
    const int tid = threadIdx.x;
    float* p = attn + (size_t)blockIdx.x * SS;

    float4 v0 = *(float4*)&p[tid * 4];
    float4 v1 = *(float4*)&p[1024 + tid * 4];

    // max
    float m = fmaxf(fmaxf(fmaxf(v0.x, v0.y), fmaxf(v0.z, v0.w)),
                    fmaxf(fmaxf(v1.x, v1.y), fmaxf(v1.z, v1.w)));
#pragma unroll
    for (int o = 16; o; o >>= 1) m = fmaxf(m, __shfl_xor_sync(~0u, m, o));
    if ((tid & 31) == 0) sred[tid >> 5] = m;
    __syncthreads();
    if (tid == 0) {
        float t = sred[0];
#pragma unroll
        for (int i = 1; i < 8; i++) t = fmaxf(t, sred[i]);
        sred[0] = t;
    }
    __syncthreads();
    m = sred[0];
    __syncthreads();

    // exp + sum
    v0.x = expf(v0.x - m); v0.y = expf(v0.y - m);
    v0.z = expf(v0.z - m); v0.w = expf(v0.w - m);
    v1.x = expf(v1.x - m); v1.y = expf(v1.y - m);
    v1.z = expf(v1.z - m); v1.w = expf(v1.w - m);
    float s = v0.x + v0.y + v0.z + v0.w + v1.x + v1.y + v1.z + v1.w;
#pragma unroll
    for (int o = 16; o; o >>= 1) s += __shfl_xor_sync(~0u, s, o);
    if ((tid & 31) == 0) sred[tid >> 5] = s;
    __syncthreads();
    if (tid == 0) {
        float t = 0.f;
#pragma unroll
        for (int i = 0; i < 8; i++) t += sred[i];
        sred[0] = t;
    }
    __syncthreads();
    float inv = 1.0f / sred[0];

    v0.x *= inv; v0.y *= inv; v0.z *= inv; v0.w *= inv;
    v1.x *= inv; v1.y *= inv; v1.z *= inv; v1.w *= inv;
    *(float4*)&p[tid * 4]        = v0;
    *(float4*)&p[1024 + tid * 4] = v1;
}

// ---------------------------------------------------------------------------
// AV: per (b,h): O[t,d] = sum_s Wgt[t,s] * V_h[s,d]; write into concat layout.
// grid: (S/64 over t, B*H). 64x64 output tile (full D=64). BK=16, K=2048.
// ---------------------------------------------------------------------------
__global__ void av_kernel(const float* __restrict__ attn,
                          const float* __restrict__ V,
                          float* __restrict__ concat)
{
    __shared__ float Wsm[16][64];
    __shared__ float Vs[16][64];

    const int tid = threadIdx.x;
    const int tx  = tid & 15;
    const int ty  = tid >> 4;
    const int t0  = blockIdx.x * 64;
    const int bh  = blockIdx.y;
    const int b   = bh >> 4;
    const int h   = bh & 15;

    const float* Ah = attn + (size_t)bh * SS * SS;
    const float* Vh = V    + (size_t)bh * SS * DD;

    const int arow = tid >> 2, akq = tid & 3;   // weights tile
    const int vrow = tid >> 4, vdq = tid & 15;  // V tile

    float acc[4][4] = {};

    for (int k0 = 0; k0 < SS; k0 += 16) {
        float4 a4 = *(const float4*)&Ah[(size_t)(t0 + arow) * SS + k0 + akq*4];
        float4 v4 = *(const float4*)&Vh[(size_t)(k0 + vrow) * DD + vdq*4];
        Wsm[akq*4+0][arow] = a4.x;
        Wsm[akq*4+1][arow] = a4.y;
        Wsm[akq*4+2][arow] = a4.z;
        Wsm[akq*4+3][arow] = a4.w;
        *(float4*)&Vs[vrow][vdq*4] = v4;
        __syncthreads();
#pragma unroll
        for (int k = 0; k < 16; k++) {
            float4 a = *(float4*)&Wsm[k][ty*4];
            float4 w = *(float4*)&Vs[k][tx*4];
            float av[4] = {a.x, a.y, a.z, a.w};
            float wv[4] = {w.x, w.y, w.z, w.w};
#pragma unroll
            for (int i = 0; i < 4; i++)
#pragma unroll
                for (int j = 0; j < 4; j++)
                    acc[i][j] += av[i] * wv[j];
        }
        __syncthreads();
    }

#pragma unroll
    for (int i = 0; i < 4; i++) {
        int t = t0 + ty*4 + i;
#pragma unroll
        for (int j = 0; j < 4; j++) {
            int d = tx*4 + j;
            concat[((size_t)(b * SS + t)) * DIM + h * DD + d] = acc[i][j];
        }
    }
}

// ---------------------------------------------------------------------------
extern "C" void kernel_launch(void* const* d_in, const int* in_sizes, int n_in,
                              void* d_out, int out_size)
{
    const float* query    = (const float*)d_in[0];
    const float* key      = (const float*)d_in[1];
    const float* value    = (const float*)d_in[2];
    const float* attnbias = (const float*)d_in[3];
    const float* paddings = (const float*)d_in[4];
    const float* wq_w = (const float*)d_in[5];
    const float* wq_b = (const float*)d_in[6];
    const float* wk_w = (const float*)d_in[7];
    const float* wk_b = (const float*)d_in[8];
    const float* wv_w = (const float*)d_in[9];
    const float* wv_b = (const float*)d_in[10];
    const float* wo_w = (const float*)d_in[11];
    const float* wo_b = (const float*)d_in[12];

    float* out  = (float*)d_out;                       // [B,S,DIM]
    float* attn = out + (size_t)BB * SS * DIM;         // [B,H,S,S] attention weights

    float *Qp, *Kp, *Vp, *Cp;
    cudaGetSymbolAddress((void**)&Qp, g_Q);
    cudaGetSymbolAddress((void**)&Kp, g_K);
    cudaGetSymbolAddress((void**)&Vp, g_V);
    cudaGetSymbolAddress((void**)&Cp, g_C);

    dim3 blk(256);
    dim3 gproj(DIM / 64, (BB * SS) / 64);   // (16, 64)

    // QKV projections (head-split outputs)
    sgemm_bias_kernel<<<gproj, blk>>>(query, wq_w, wq_b, Qp, BB*SS, DIM, DIM, 1);
    sgemm_bias_kernel<<<gproj, blk>>>(key,   wk_w, wk_b, Kp, BB*SS, DIM, DIM, 1);
    sgemm_bias_kernel<<<gproj, blk>>>(value, wv_w, wv_b, Vp, BB*SS, DIM, DIM, 1);

    // Logits + bias + mask -> attn region of d_out
    dim3 glog(SS / 64, SS / 64, BB * HH);   // (32, 32, 32)
    logits_kernel<<<glog, blk>>>(Qp, Kp, attnbias, paddings, attn);

    // Row softmax in-place
    softmax_kernel<<<BB * HH * SS, 256>>>(attn);

    // AV -> concat
    dim3 gav(SS / 64, BB * HH);             // (32, 32)
    av_kernel<<<gav, blk>>>(attn, Vp, Cp);

    // Output projection -> out
    sgemm_bias_kernel<<<gproj, blk>>>(Cp, wo_w, wo_b, out, BB*SS, DIM, DIM, 0);
}

// round 4
// speedup vs baseline: 1.8051x; 1.7959x over previous
#include <cuda_runtime.h>
#include <cuda_bf16.h>
#include <stdint.h>

#define BB  2
#define SS  2048
#define DIM 1024
#define HH  16
#define DD  64
#define MT  (BB*SS)
#define NBH (BB*HH)

// ---- device scratch (allocation-free rule) ----
__device__ __nv_bfloat16 g_xh[3][MT*DIM], g_xl[3][MT*DIM];     // split q,k,v inputs
__device__ __nv_bfloat16 g_twh[4][DIM*DIM], g_twl[4][DIM*DIM]; // WT hi/lo [N][K]
__device__ __nv_bfloat16 g_qh[NBH*SS*DD], g_ql[NBH*SS*DD];     // [bh,s,d]
__device__ __nv_bfloat16 g_kh[NBH*SS*DD], g_kl[NBH*SS*DD];
__device__ __nv_bfloat16 g_vh[NBH*SS*DD], g_vl[NBH*SS*DD];
__device__ __nv_bfloat16 g_vth[NBH*DD*SS], g_vtl[NBH*DD*SS];   // VT [bh,d,s]
__device__ __nv_bfloat16 g_ch[MT*DIM], g_cl[MT*DIM];           // concat split

// ---- helpers ----
__device__ __forceinline__ uint32_t s2u(const void* p){
    uint32_t a;
    asm("{ .reg .u64 t; cvta.to.shared.u64 t, %1; cvt.u32.u64 %0, t; }":"=r"(a):"l"(p));
    return a;
}
__device__ __forceinline__ void bsplit(float v, __nv_bfloat16& h, __nv_bfloat16& l){
    h = __float2bfloat16(v);
    l = __float2bfloat16(v - __bfloat162float(h));
}
__device__ __forceinline__ uint32_t pk2(__nv_bfloat16 a, __nv_bfloat16 b){
    __nv_bfloat162 t(a, b); return *(uint32_t*)&t;
}
__device__ __forceinline__ void ldmx4(uint32_t* r, uint32_t addr){
    asm volatile("ldmatrix.sync.aligned.m8n8.x4.shared.b16 {%0,%1,%2,%3}, [%4];"
        : "=r"(r[0]),"=r"(r[1]),"=r"(r[2]),"=r"(r[3]) : "r"(addr));
}
__device__ __forceinline__ void ldmx2(uint32_t* r, uint32_t addr){
    asm volatile("ldmatrix.sync.aligned.m8n8.x2.shared.b16 {%0,%1}, [%2];"
        : "=r"(r[0]),"=r"(r[1]) : "r"(addr));
}
__device__ __forceinline__ void mma16816(float* c, const uint32_t* a, const uint32_t* b){
    asm volatile("mma.sync.aligned.m16n8k16.row.col.f32.bf16.bf16.f32 "
        "{%0,%1,%2,%3}, {%4,%5,%6,%7}, {%8,%9}, {%0,%1,%2,%3};"
        : "+f"(c[0]),"+f"(c[1]),"+f"(c[2]),"+f"(c[3])
        : "r"(a[0]),"r"(a[1]),"r"(a[2]),"r"(a[3]), "r"(b[0]),"r"(b[1]));
}

// ---- fp32 -> bf16 hi/lo split ----
__global__ void split_kernel(const float* __restrict__ x,
                             __nv_bfloat16* __restrict__ h,
                             __nv_bfloat16* __restrict__ l)
{
    int i = (blockIdx.x * blockDim.x + threadIdx.x) * 4;
    float4 v = *(const float4*)&x[i];
    __nv_bfloat16 h0,h1,h2,h3,l0,l1,l2,l3;
    bsplit(v.x,h0,l0); bsplit(v.y,h1,l1); bsplit(v.z,h2,l2); bsplit(v.w,h3,l3);
    uint2 hp = { pk2(h0,h1), pk2(h2,h3) };
    uint2 lp = { pk2(l0,l1), pk2(l2,l3) };
    *(uint2*)&h[i] = hp; *(uint2*)&l[i] = lp;
}

// ---- W[K,N] -> WT[N,K] hi/lo ----
__global__ void wtrans_kernel(const float* __restrict__ W,
                              __nv_bfloat16* __restrict__ Th,
                              __nv_bfloat16* __restrict__ Tl)
{
    __shared__ float t[32][33];
    int bx = blockIdx.x * 32, by = blockIdx.y * 32;
    int x = threadIdx.x, y = threadIdx.y;
    for (int yy = y; yy < 32; yy += 8)
        t[yy][x] = W[(size_t)(by + yy) * DIM + bx + x];
    __syncthreads();
    for (int yy = y; yy < 32; yy += 8) {
        __nv_bfloat16 h, l; bsplit(t[x][yy], h, l);
        Th[(size_t)(bx + yy) * DIM + by + x] = h;
        Tl[(size_t)(bx + yy) * DIM + by + x] = l;
    }
}

// ---- V [bh,s,d] -> VT [bh,d,s] (bf16) ----
__global__ void vtrans_kernel(const __nv_bfloat16* __restrict__ V,
                              __nv_bfloat16* __restrict__ VT)
{
    __shared__ __nv_bfloat16 t[64][65];
    int bh = blockIdx.y, s0 = blockIdx.x * 64;
    int tid = threadIdx.x;
    for (int i = tid; i < 64*64; i += 256) {
        int r = i >> 6, c = i & 63;
        t[r][c] = V[((size_t)bh * SS + s0 + r) * DD + c];
    }
    __syncthreads();
    for (int i = tid; i < 64*64; i += 256) {
        int r = i >> 6, c = i & 63;
        VT[((size_t)bh * DD + r) * SS + s0 + c] = t[c][r];
    }
}

// ===========================================================================
// Generic split-bf16 mma.sync GEMM: D[M,N] = A[M,K] @ B[N,K]^T
// MODE 0: proj -> split-head bf16 hi/lo (+bias)    grid (8, 32)
// MODE 1: proj -> fp32 out (+bias)                 grid (8, 32)
// MODE 2: logits (K=64) -> fp32 attn               grid (16, 16, 32)
// MODE 3: AV (A fp32 in, K=2048, N=64) -> bf16 concat   grid (16, 32)
// 256 threads = 8 warps (2m x 4n). Warp tile 64 x (WNT*8).
// ===========================================================================
#define STRD 40   // smem row stride in bf16 elems (80B: conflict-free ldmatrix)

template<int MODE>
__global__ __launch_bounds__(256) void mma_gemm_kernel(
    const __nv_bfloat16* __restrict__ Ah, const __nv_bfloat16* __restrict__ Al,
    const float* __restrict__ Af,
    const __nv_bfloat16* __restrict__ Bh, const __nv_bfloat16* __restrict__ Bl,
    const float* __restrict__ bias,
    float* __restrict__ outF,
    __nv_bfloat16* __restrict__ Oh, __nv_bfloat16* __restrict__ Ol)
{
    constexpr int WNT   = (MODE == 3) ? 2 : 4;
    constexpr int KTOT  = (MODE == 2) ? 64 : (MODE == 3 ? 2048 : 1024);
    constexpr int LDA   = (MODE == 2) ? 64 : (MODE == 3 ? 2048 : 1024);
    constexpr int LDB   = (MODE == 2) ? 64 : (MODE == 3 ? 2048 : 1024);
    constexpr int BROWS = (MODE == 3) ? 64 : 128;

    __shared__ __nv_bfloat16 sAh[128*STRD], sAl[128*STRD];
    __shared__ __nv_bfloat16 sBh[128*STRD], sBl[128*STRD];

    const int tid = threadIdx.x, lane = tid & 31, wid = tid >> 5;
    const int wm = wid >> 2, wn = wid & 3;

    int m0, n0, bh = 0;
    size_t arow0, brow0;
    if (MODE <= 1)      { n0 = blockIdx.x*128; m0 = blockIdx.y*128; arow0 = m0; brow0 = n0; }
    else if (MODE == 2) { bh = blockIdx.z; n0 = blockIdx.x*128; m0 = blockIdx.y*128;
                          arow0 = (size_t)bh*SS + m0; brow0 = (size_t)bh*SS + n0; }
    else                { bh = blockIdx.y; m0 = blockIdx.x*128; n0 = 0;
                          arow0 = (size_t)bh*SS + m0; brow0 = (size_t)bh*DD; }

    const __nv_bfloat16* Abh = (MODE == 3) ? nullptr : (Ah + arow0 * LDA);
    const __nv_bfloat16* Abl = (MODE == 3) ? nullptr : (Al + arow0 * LDA);
    const float*         Abf = (MODE == 3) ? (Af + arow0 * LDA) : nullptr;
    const __nv_bfloat16* Bbh = Bh + brow0 * LDB;
    const __nv_bfloat16* Bbl = Bl + brow0 * LDB;

    float c[4][WNT][4] = {};

    const uint32_t aAh = s2u(sAh), aAl = s2u(sAl);
    const uint32_t aBh = s2u(sBh), aBl = s2u(sBl);

    for (int k0 = 0; k0 < KTOT; k0 += 32) {
        __syncthreads();
        if (MODE == 3) {
            for (int idx = tid; idx < 128*8; idx += 256) {
                int r = idx >> 3, cc = idx & 7;
                float4 w = *(const float4*)&Abf[(size_t)r*LDA + k0 + cc*4];
                __nv_bfloat16 h0,h1,h2,h3,l0,l1,l2,l3;
                bsplit(w.x,h0,l0); bsplit(w.y,h1,l1);
                bsplit(w.z,h2,l2); bsplit(w.w,h3,l3);
                uint2 hp = { pk2(h0,h1), pk2(h2,h3) };
                uint2 lp = { pk2(l0,l1), pk2(l2,l3) };
                *(uint2*)&sAh[r*STRD + cc*4] = hp;
                *(uint2*)&sAl[r*STRD + cc*4] = lp;
            }
        } else {
            for (int idx = tid; idx < 128*4; idx += 256) {
                int r = idx >> 2, cc = idx & 3;
                *(uint4*)&sAh[r*STRD + cc*8] = *(const uint4*)&Abh[(size_t)r*LDA + k0 + cc*8];
                *(uint4*)&sAl[r*STRD + cc*8] = *(const uint4*)&Abl[(size_t)r*LDA + k0 + cc*8];
            }
        }
        for (int idx = tid; idx < BROWS*4; idx += 256) {
            int r = idx >> 2, cc = idx & 3;
            *(uint4*)&sBh[r*STRD + cc*8] = *(const uint4*)&Bbh[(size_t)r*LDB + k0 + cc*8];
            *(uint4*)&sBl[r*STRD + cc*8] = *(const uint4*)&Bbl[(size_t)r*LDB + k0 + cc*8];
        }
        __syncthreads();

#pragma unroll
        for (int h = 0; h < 2; h++) {
            uint32_t fAh[4][4], fAl[4][4], fBh[WNT][2], fBl[WNT][2];
            const int ar = wm*64 + (lane & 15);
            const int ac = h*16 + ((lane >> 4) << 3);
#pragma unroll
            for (int mi = 0; mi < 4; mi++) {
                uint32_t off = (uint32_t)((ar + mi*16)*STRD + ac) * 2;
                ldmx4(fAh[mi], aAh + off);
                ldmx4(fAl[mi], aAl + off);
            }
            const int br = wn*(WNT*8) + (lane & 7);
            const int bc = h*16 + ((lane >> 3) & 1)*8;
#pragma unroll
            for (int ni = 0; ni < WNT; ni++) {
                uint32_t off = (uint32_t)((br + ni*8)*STRD + bc) * 2;
                ldmx2(fBh[ni], aBh + off);
                ldmx2(fBl[ni], aBl + off);
            }
#pragma unroll
            for (int mi = 0; mi < 4; mi++)
#pragma unroll
                for (int ni = 0; ni < WNT; ni++) {
                    mma16816(c[mi][ni], fAh[mi], fBh[ni]);
                    mma16816(c[mi][ni], fAh[mi], fBl[ni]);
                    mma16816(c[mi][ni], fAl[mi], fBh[ni]);
                }
        }
    }

    // ---- epilogue ----
    const int g = lane >> 2, tg = lane & 3;
#pragma unroll
    for (int mi = 0; mi < 4; mi++)
#pragma unroll
        for (int ni = 0; ni < WNT; ni++) {
            const int m = m0 + wm*64 + mi*16 + g;
            const int n = n0 + wn*(WNT*8) + ni*8 + tg*2;
            const float v00 = c[mi][ni][0], v01 = c[mi][ni][1];
            const float v10 = c[mi][ni][2], v11 = c[mi][ni][3];
            if (MODE == 1) {
                const float b0 = bias[n], b1 = bias[n+1];
                float2 r0 = { v00 + b0, v01 + b1 };
                float2 r1 = { v10 + b0, v11 + b1 };
                *(float2*)&outF[(size_t)m*DIM + n]     = r0;
                *(float2*)&outF[(size_t)(m+8)*DIM + n] = r1;
            } else if (MODE == 0) {
                const float b0 = bias[n], b1 = bias[n+1];
                const int b = m >> 11, hd = n >> 6, d = n & 63;
                const size_t base = (((size_t)(b*HH + hd))*SS + (m & 2047))*DD + d;
                __nv_bfloat16 h0,h1,h2,h3,l0,l1,l2,l3;
                bsplit(v00 + b0, h0, l0); bsplit(v01 + b1, h1, l1);
                bsplit(v10 + b0, h2, l2); bsplit(v11 + b1, h3, l3);
                *(uint32_t*)&Oh[base]        = pk2(h0, h1);
                *(uint32_t*)&Ol[base]        = pk2(l0, l1);
                *(uint32_t*)&Oh[base + 8*DD] = pk2(h2, h3);
                *(uint32_t*)&Ol[base + 8*DD] = pk2(l2, l3);
            } else if (MODE == 2) {
                float* op = &outF[((size_t)bh*SS + m)*SS + n];
                float2 r0 = { v00, v01 };
                float2 r1 = { v10, v11 };
                *(float2*)op            = r0;
                *(float2*)(op + 8*SS)   = r1;
            } else {  // MODE 3
                const int b = bh >> 4, hd = bh & 15;
                const size_t base = ((size_t)(b*SS + m))*DIM + hd*DD + n;
                __nv_bfloat16 h0,h1,h2,h3,l0,l1,l2,l3;
                bsplit(v00, h0, l0); bsplit(v01, h1, l1);
                bsplit(v10, h2, l2); bsplit(v11, h3, l3);
                *(uint32_t*)&Oh[base]         = pk2(h0, h1);
                *(uint32_t*)&Ol[base]         = pk2(l0, l1);
                *(uint32_t*)&Oh[base + 8*DIM] = pk2(h2, h3);
                *(uint32_t*)&Ol[base + 8*DIM] = pk2(l2, l3);
            }
        }
}

// ---- softmax fused with scale + bias + mask; in-place on attn ----
__global__ void softmax_kernel(float* __restrict__ attn,
                               const float* __restrict__ bias4d,
                               const float* __restrict__ pad)
{
    __shared__ float sred[8];
    const int tid = threadIdx.x;
    const int row = blockIdx.x;          // over BH*SS
    const int b = row >> 15, t = row & 2047;
    float* p = attn + (size_t)row * SS;
    const float* bp = bias4d + (size_t)row * SS;
    const float mt = 1.0f - pad[b * SS + t];

    float v[8];
    {
        float4 a0 = *(float4*)&p[tid*4],      b0 = *(const float4*)&bp[tid*4];
        float4 a1 = *(float4*)&p[1024+tid*4], b1 = *(const float4*)&bp[1024+tid*4];
        float4 m0 = *(const float4*)&pad[b*SS + tid*4];
        float4 m1 = *(const float4*)&pad[b*SS + 1024 + tid*4];
        v[0]=a0.x*0.125f+b0.x-1e9f*(1.f-mt*(1.f-m0.x));
        v[1]=a0.y*0.125f+b0.y-1e9f*(1.f-mt*(1.f-m0.y));
        v[2]=a0.z*0.125f+b0.z-1e9f*(1.f-mt*(1.f-m0.z));
        v[3]=a0.w*0.125f+b0.w-1e9f*(1.f-mt*(1.f-m0.w));
        v[4]=a1.x*0.125f+b1.x-1e9f*(1.f-mt*(1.f-m1.x));
        v[5]=a1.y*0.125f+b1.y-1e9f*(1.f-mt*(1.f-m1.y));
        v[6]=a1.z*0.125f+b1.z-1e9f*(1.f-mt*(1.f-m1.z));
        v[7]=a1.w*0.125f+b1.w-1e9f*(1.f-mt*(1.f-m1.w));
    }
    float m = v[0];
#pragma unroll
    for (int i = 1; i < 8; i++) m = fmaxf(m, v[i]);
#pragma unroll
    for (int o = 16; o; o >>= 1) m = fmaxf(m, __shfl_xor_sync(~0u, m, o));
    if ((tid & 31) == 0) sred[tid >> 5] = m;
    __syncthreads();
    if (tid == 0) { float x = sred[0];
#pragma unroll
        for (int i = 1; i < 8; i++) x = fmaxf(x, sred[i]); sred[0] = x; }
    __syncthreads();
    m = sred[0];
    __syncthreads();
    float s = 0.f;
#pragma unroll
    for (int i = 0; i < 8; i++) { v[i] = expf(v[i] - m); s += v[i]; }
#pragma unroll
    for (int o = 16; o; o >>= 1) s += __shfl_xor_sync(~0u, s, o);
    if ((tid & 31) == 0) sred[tid >> 5] = s;
    __syncthreads();
    if (tid == 0) { float x = 0.f;
#pragma unroll
        for (int i = 0; i < 8; i++) x += sred[i]; sred[0] = x; }
    __syncthreads();
    float inv = 1.0f / sred[0];
    float4 o0 = { v[0]*inv, v[1]*inv, v[2]*inv, v[3]*inv };
    float4 o1 = { v[4]*inv, v[5]*inv, v[6]*inv, v[7]*inv };
    *(float4*)&p[tid*4] = o0;
    *(float4*)&p[1024+tid*4] = o1;
}

// ---------------------------------------------------------------------------
extern "C" void kernel_launch(void* const* d_in, const int* in_sizes, int n_in,
                              void* d_out, int out_size)
{
    const float* xin[3] = { (const float*)d_in[0], (const float*)d_in[1], (const float*)d_in[2] };
    const float* attnbias = (const float*)d_in[3];
    const float* paddings = (const float*)d_in[4];
    const float* ww[4] = { (const float*)d_in[5], (const float*)d_in[7],
                           (const float*)d_in[9], (const float*)d_in[11] };
    const float* wb[4] = { (const float*)d_in[6], (const float*)d_in[8],
                           (const float*)d_in[10], (const float*)d_in[12] };

    float* out  = (float*)d_out;
    float* attn = out + (size_t)MT * DIM;

    __nv_bfloat16 *xh, *xl, *twh, *twl, *qh, *ql, *kh, *kl, *vh, *vl, *vth, *vtl, *ch, *cl;
    cudaGetSymbolAddress((void**)&xh, g_xh);   cudaGetSymbolAddress((void**)&xl, g_xl);
    cudaGetSymbolAddress((void**)&twh, g_twh); cudaGetSymbolAddress((void**)&twl, g_twl);
    cudaGetSymbolAddress((void**)&qh, g_qh);   cudaGetSymbolAddress((void**)&ql, g_ql);
    cudaGetSymbolAddress((void**)&kh, g_kh);   cudaGetSymbolAddress((void**)&kl, g_kl);
    cudaGetSymbolAddress((void**)&vh, g_vh);   cudaGetSymbolAddress((void**)&vl, g_vl);
    cudaGetSymbolAddress((void**)&vth, g_vth); cudaGetSymbolAddress((void**)&vtl, g_vtl);
    cudaGetSymbolAddress((void**)&ch, g_ch);   cudaGetSymbolAddress((void**)&cl, g_cl);

    const size_t NX = (size_t)MT * DIM;
    const size_t NW = (size_t)DIM * DIM;

    // split inputs
    for (int i = 0; i < 3; i++)
        split_kernel<<<NX/1024, 256>>>(xin[i], xh + i*NX, xl + i*NX);
    // transpose+split weights
    for (int i = 0; i < 4; i++)
        wtrans_kernel<<<dim3(32,32), dim3(32,8)>>>(ww[i], twh + i*NW, twl + i*NW);

    dim3 gproj(DIM/128, MT/128);   // (8, 32)
    __nv_bfloat16* oh[3] = { qh, kh, vh };
    __nv_bfloat16* ol[3] = { ql, kl, vl };
    for (int i = 0; i < 3; i++)
        mma_gemm_kernel<0><<<gproj, 256>>>(xh + i*NX, xl + i*NX, nullptr,
                                           twh + i*NW, twl + i*NW,
                                           wb[i], nullptr, oh[i], ol[i]);

    // V transpose (hi, lo)
    vtrans_kernel<<<dim3(32, NBH), 256>>>(vh, vth);
    vtrans_kernel<<<dim3(32, NBH), 256>>>(vl, vtl);

    // raw logits -> attn
    mma_gemm_kernel<2><<<dim3(16,16,NBH), 256>>>(qh, ql, nullptr, kh, kl,
                                                 nullptr, attn, nullptr, nullptr);

    // softmax (scale+bias+mask fused), in-place
    softmax_kernel<<<NBH*SS, 256>>>(attn, attnbias, paddings);

    // AV -> concat split
    mma_gemm_kernel<3><<<dim3(16, NBH), 256>>>(nullptr, nullptr, attn, vth, vtl,
                                               nullptr, nullptr, ch, cl);

    // output projection -> fp32 out
    mma_gemm_kernel<1><<<gproj, 256>>>(ch, cl, nullptr, twh + 3*NW, twl + 3*NW,
                                       wb[3], out, nullptr, nullptr);
}

// round 6
// speedup vs baseline: 2.2351x; 1.2382x over previous
#include <cuda_runtime.h>
#include <cuda_bf16.h>
#include <stdint.h>

#define BB  2
#define SS  2048
#define DIM 1024
#define HH  16
#define DD  64
#define MT  (BB*SS)
#define NBH (BB*HH)

// ---- device scratch ----
__device__ __nv_bfloat16 g_xh[3][MT*DIM], g_xl[3][MT*DIM];     // split q,k,v inputs
__device__ __nv_bfloat16 g_twh[4][DIM*DIM], g_twl[4][DIM*DIM]; // WT hi/lo [N][K]
__device__ __nv_bfloat16 g_ph[3][NBH*SS*DD], g_pl[3][NBH*SS*DD]; // Q,K,V head-split
__device__ __nv_bfloat16 g_vth[NBH*DD*SS], g_vtl[NBH*DD*SS];   // VT [bh,d,s]
__device__ __nv_bfloat16 g_ch[MT*DIM], g_cl[MT*DIM];           // concat split

#define STRD 40   // smem row stride (bf16 elems) = 80B

// ---- helpers ----
__device__ __forceinline__ uint32_t s2u(const void* p){
    uint32_t a;
    asm("{ .reg .u64 t; cvta.to.shared.u64 t, %1; cvt.u32.u64 %0, t; }":"=r"(a):"l"(p));
    return a;
}
__device__ __forceinline__ void bsplit(float v, __nv_bfloat16& h, __nv_bfloat16& l){
    h = __float2bfloat16(v);
    l = __float2bfloat16(v - __bfloat162float(h));
}
__device__ __forceinline__ uint32_t pk2(__nv_bfloat16 a, __nv_bfloat16 b){
    __nv_bfloat162 t(a, b); return *(uint32_t*)&t;
}
__device__ __forceinline__ void ldmx4(uint32_t* r, uint32_t addr){
    asm volatile("ldmatrix.sync.aligned.m8n8.x4.shared.b16 {%0,%1,%2,%3}, [%4];"
        : "=r"(r[0]),"=r"(r[1]),"=r"(r[2]),"=r"(r[3]) : "r"(addr));
}
__device__ __forceinline__ void ldmx2(uint32_t* r, uint32_t addr){
    asm volatile("ldmatrix.sync.aligned.m8n8.x2.shared.b16 {%0,%1}, [%2];"
        : "=r"(r[0]),"=r"(r[1]) : "r"(addr));
}
__device__ __forceinline__ void mma16816(float* c, const uint32_t* a, const uint32_t* b){
    asm volatile("mma.sync.aligned.m16n8k16.row.col.f32.bf16.bf16.f32 "
        "{%0,%1,%2,%3}, {%4,%5,%6,%7}, {%8,%9}, {%0,%1,%2,%3};"
        : "+f"(c[0]),"+f"(c[1]),"+f"(c[2]),"+f"(c[3])
        : "r"(a[0]),"r"(a[1]),"r"(a[2]),"r"(a[3]), "r"(b[0]),"r"(b[1]));
}
__device__ __forceinline__ void cpa16(uint32_t s, const void* g){
    asm volatile("cp.async.cg.shared.global [%0], [%1], 16;" :: "r"(s), "l"(g));
}
#define CPA_COMMIT() asm volatile("cp.async.commit_group;" ::: "memory")
#define CPA_WAIT1()  asm volatile("cp.async.wait_group 1;" ::: "memory")
#define CPA_WAIT0()  asm volatile("cp.async.wait_group 0;" ::: "memory")

// ---- warp-tile compute: 64 x (WNT*8), 3 split products, K=32 per call ----
template<int WNT>
__device__ __forceinline__ void tile_compute(
    uint32_t aAh, uint32_t aAl, uint32_t aBh, uint32_t aBl,
    int wm, int wn, int lane, float c[4][WNT][4])
{
#pragma unroll
    for (int h = 0; h < 2; h++) {
        uint32_t fAh[4][4], fAl[4][4], fBh[WNT][2], fBl[WNT][2];
        const int ar = wm*64 + (lane & 15);
        const int ac = h*16 + ((lane >> 4) << 3);
#pragma unroll
        for (int mi = 0; mi < 4; mi++) {
            uint32_t off = (uint32_t)((ar + mi*16)*STRD + ac) * 2;
            ldmx4(fAh[mi], aAh + off);
            ldmx4(fAl[mi], aAl + off);
        }
        const int br = wn*(WNT*8) + (lane & 7);
        const int bc = h*16 + ((lane >> 3) & 1)*8;
#pragma unroll
        for (int ni = 0; ni < WNT; ni++) {
            uint32_t off = (uint32_t)((br + ni*8)*STRD + bc) * 2;
            ldmx2(fBh[ni], aBh + off);
            ldmx2(fBl[ni], aBl + off);
        }
#pragma unroll
        for (int mi = 0; mi < 4; mi++)
#pragma unroll
            for (int ni = 0; ni < WNT; ni++) {
                mma16816(c[mi][ni], fAh[mi], fBh[ni]);
                mma16816(c[mi][ni], fAh[mi], fBl[ni]);
                mma16816(c[mi][ni], fAl[mi], fBh[ni]);
            }
    }
}

// ---- fp32 -> bf16 hi/lo split ----
__global__ void split_kernel(const float* __restrict__ x,
                             __nv_bfloat16* __restrict__ h,
                             __nv_bfloat16* __restrict__ l)
{
    int i = (blockIdx.x * blockDim.x + threadIdx.x) * 4;
    float4 v = *(const float4*)&x[i];
    __nv_bfloat16 h0,h1,h2,h3,l0,l1,l2,l3;
    bsplit(v.x,h0,l0); bsplit(v.y,h1,l1); bsplit(v.z,h2,l2); bsplit(v.w,h3,l3);
    uint2 hp = { pk2(h0,h1), pk2(h2,h3) };
    uint2 lp = { pk2(l0,l1), pk2(l2,l3) };
    *(uint2*)&h[i] = hp; *(uint2*)&l[i] = lp;
}

// ---- W[K,N] -> WT[N,K] hi/lo ----
__global__ void wtrans_kernel(const float* __restrict__ W,
                              __nv_bfloat16* __restrict__ Th,
                              __nv_bfloat16* __restrict__ Tl)
{
    __shared__ float t[32][33];
    int bx = blockIdx.x * 32, by = blockIdx.y * 32;
    int x = threadIdx.x, y = threadIdx.y;
    for (int yy = y; yy < 32; yy += 8)
        t[yy][x] = W[(size_t)(by + yy) * DIM + bx + x];
    __syncthreads();
    for (int yy = y; yy < 32; yy += 8) {
        __nv_bfloat16 h, l; bsplit(t[x][yy], h, l);
        Th[(size_t)(bx + yy) * DIM + by + x] = h;
        Tl[(size_t)(bx + yy) * DIM + by + x] = l;
    }
}

// ---- V [bh,s,d] -> VT [bh,d,s] (bf16) ----
__global__ void vtrans_kernel(const __nv_bfloat16* __restrict__ V,
                              __nv_bfloat16* __restrict__ VT)
{
    __shared__ __nv_bfloat16 t[64][65];
    int bh = blockIdx.y, s0 = blockIdx.x * 64;
    int tid = threadIdx.x;
    for (int i = tid; i < 64*64; i += 256) {
        int r = i >> 6, c = i & 63;
        t[r][c] = V[((size_t)bh * SS + s0 + r) * DD + c];
    }
    __syncthreads();
    for (int i = tid; i < 64*64; i += 256) {
        int r = i >> 6, c = i & 63;
        VT[((size_t)bh * DD + r) * SS + s0 + c] = t[c][r];
    }
}

// ===========================================================================
// Pipelined bf16 GEMM (cp.async 2-stage): D[M,N] = A[M,K] @ B[N,K]^T
// MODE 0: QKV proj (z=0..2) -> split-head bf16 hi/lo (+bias)  grid (8,32,3)
// MODE 1: out proj -> fp32 (+bias)                            grid (8,32)
// MODE 2: logits (K=64) -> fp32 attn                          grid (16,16,32)
// dynamic smem = 8 * 10240 = 81920 B
// ===========================================================================
template<int MODE>
__global__ __launch_bounds__(256) void gemm_pipe_kernel(
    const __nv_bfloat16* __restrict__ Ah_, const __nv_bfloat16* __restrict__ Al_,
    const __nv_bfloat16* __restrict__ Bh_, const __nv_bfloat16* __restrict__ Bl_,
    const float* __restrict__ b0, const float* __restrict__ b1, const float* __restrict__ b2,
    float* __restrict__ outF,
    __nv_bfloat16* __restrict__ Oh_, __nv_bfloat16* __restrict__ Ol_)
{
    constexpr int KTOT = (MODE == 2) ? 64 : 1024;
    constexpr int LDAB = (MODE == 2) ? 64 : 1024;
    constexpr int NT   = KTOT / 32;

    extern __shared__ char sm[];
    const uint32_t sb = s2u(sm);
    const uint32_t aAH[2] = { sb,          sb + 10240 };
    const uint32_t aAL[2] = { sb + 20480,  sb + 30720 };
    const uint32_t aBH[2] = { sb + 40960,  sb + 51200 };
    const uint32_t aBL[2] = { sb + 61440,  sb + 71680 };

    const int tid = threadIdx.x, lane = tid & 31, wid = tid >> 5;
    const int wm = wid >> 2, wn = wid & 3;

    int m0, n0, bh = 0, z = 0;
    size_t arow0, brow0;
    const size_t NX = (size_t)MT * DIM, NW = (size_t)DIM * DIM;
    if (MODE == 0)      { z = blockIdx.z; n0 = blockIdx.x*128; m0 = blockIdx.y*128;
                          arow0 = m0; brow0 = n0; }
    else if (MODE == 1) { n0 = blockIdx.x*128; m0 = blockIdx.y*128; arow0 = m0; brow0 = n0; }
    else                { bh = blockIdx.z; n0 = blockIdx.x*128; m0 = blockIdx.y*128;
                          arow0 = (size_t)bh*SS + m0; brow0 = (size_t)bh*SS + n0; }

    const __nv_bfloat16* Abh = (MODE == 0 ? Ah_ + z*NX : Ah_) + arow0 * LDAB;
    const __nv_bfloat16* Abl = (MODE == 0 ? Al_ + z*NX : Al_) + arow0 * LDAB;
    const __nv_bfloat16* Bbh = (MODE == 0 ? Bh_ + z*NW : Bh_) + brow0 * LDAB;
    const __nv_bfloat16* Bbl = (MODE == 0 ? Bl_ + z*NW : Bl_) + brow0 * LDAB;
    const float* bias = (MODE == 0) ? (z == 0 ? b0 : (z == 1 ? b1 : b2)) : b0;

    float c[4][4][4] = {};

    auto load_stage = [&](int st, int k0){
        for (int idx = tid; idx < 512; idx += 256) {
            int r = idx >> 2, cc = idx & 3;
            uint32_t so = (uint32_t)r*80 + cc*16;
            size_t go = (size_t)r*LDAB + k0 + cc*8;
            cpa16(aAH[st] + so, Abh + go);
            cpa16(aAL[st] + so, Abl + go);
            cpa16(aBH[st] + so, Bbh + go);
            cpa16(aBL[st] + so, Bbl + go);
        }
    };

    load_stage(0, 0);  CPA_COMMIT();
    if (NT > 1) { load_stage(1, 32); }
    CPA_COMMIT();

    for (int kt = 0; kt < NT; kt++) {
        if (kt + 1 < NT) { CPA_WAIT1(); } else { CPA_WAIT0(); }
        __syncthreads();
        const int st = kt & 1;
        tile_compute<4>(aAH[st], aAL[st], aBH[st], aBL[st], wm, wn, lane, c);
        __syncthreads();
        if (kt + 2 < NT) { load_stage(st, (kt + 2) * 32); CPA_COMMIT(); }
    }

    // ---- epilogue ----
    const int g = lane >> 2, tg = lane & 3;
#pragma unroll
    for (int mi = 0; mi < 4; mi++)
#pragma unroll
        for (int ni = 0; ni < 4; ni++) {
            const int m = m0 + wm*64 + mi*16 + g;
            const int n = n0 + wn*32 + ni*8 + tg*2;
            const float v00 = c[mi][ni][0], v01 = c[mi][ni][1];
            const float v10 = c[mi][ni][2], v11 = c[mi][ni][3];
            if (MODE == 1) {
                const float q0 = b0[n], q1 = b0[n+1];
                float2 r0 = { v00 + q0, v01 + q1 };
                float2 r1 = { v10 + q0, v11 + q1 };
                *(float2*)&outF[(size_t)m*DIM + n]     = r0;
                *(float2*)&outF[(size_t)(m+8)*DIM + n] = r1;
            } else if (MODE == 0) {
                const float q0 = bias[n], q1 = bias[n+1];
                const int b = m >> 11, hd = n >> 6, d = n & 63;
                const size_t base = z*NX + (((size_t)(b*HH + hd))*SS + (m & 2047))*DD + d;
                __nv_bfloat16 h0,h1,h2,h3,l0,l1,l2,l3;
                bsplit(v00 + q0, h0, l0); bsplit(v01 + q1, h1, l1);
                bsplit(v10 + q0, h2, l2); bsplit(v11 + q1, h3, l3);
                *(uint32_t*)&Oh_[base]        = pk2(h0, h1);
                *(uint32_t*)&Ol_[base]        = pk2(l0, l1);
                *(uint32_t*)&Oh_[base + 8*DD] = pk2(h2, h3);
                *(uint32_t*)&Ol_[base + 8*DD] = pk2(l2, l3);
            } else {
                float* op = &outF[((size_t)bh*SS + m)*SS + n];
                float2 r0 = { v00, v01 };
                float2 r1 = { v10, v11 };
                *(float2*)op          = r0;
                *(float2*)(op + 8*SS) = r1;
            }
        }
}

// ===========================================================================
// Pipelined AV: O[bh][t,d] = sum_s W[t,s] V[s,d]; A fp32 staged via cp.async,
// converted smem->smem to bf16 hi/lo. B = VT bf16 hi/lo (64 rows). grid (16,32).
// dynamic smem = 77824 B
// ===========================================================================
__global__ __launch_bounds__(256) void av_pipe_kernel(
    const float* __restrict__ Af,
    const __nv_bfloat16* __restrict__ VTh, const __nv_bfloat16* __restrict__ VTl,
    __nv_bfloat16* __restrict__ Ch, __nv_bfloat16* __restrict__ Cl)
{
    extern __shared__ char sm[];
    const uint32_t sb = s2u(sm);
    const uint32_t aAF[2] = { sb, sb + 18432 };        // fp32 128 x 32, stride 36 floats
    const uint32_t aAH = sb + 36864, aAL = sb + 47104; // bf16 128 x 32, stride 40
    const uint32_t aBH[2] = { sb + 57344, sb + 62464 };
    const uint32_t aBL[2] = { sb + 67584, sb + 72704 };

    const int tid = threadIdx.x, lane = tid & 31, wid = tid >> 5;
    const int wm = wid >> 2, wn = wid & 3;
    const int bh = blockIdx.y, b = bh >> 4, hd = bh & 15;
    const int m0 = blockIdx.x * 128;

    const float* Abf = Af + ((size_t)bh*SS + m0) * SS;
    const __nv_bfloat16* Bbh = VTh + (size_t)bh*DD*SS;
    const __nv_bfloat16* Bbl = VTl + (size_t)bh*DD*SS;

    float c[4][2][4] = {};

    auto load_stage = [&](int st, int k0){
        for (int idx = tid; idx < 1024; idx += 256) {    // A fp32: 128 rows x 8 chunks
            int r = idx >> 3, cc = idx & 7;
            cpa16(aAF[st] + (uint32_t)r*144 + cc*16, Abf + (size_t)r*SS + k0 + cc*4);
        }
        for (int idx = tid; idx < 256; idx += 256) {     // B: 64 rows x 4 chunks (hi+lo)
            int r = idx >> 2, cc = idx & 3;
            uint32_t so = (uint32_t)r*80 + cc*16;
            size_t go = (size_t)r*SS + k0 + cc*8;
            cpa16(aBH[st] + so, Bbh + go);
            cpa16(aBL[st] + so, Bbl + go);
        }
    };

    load_stage(0, 0);  CPA_COMMIT();
    load_stage(1, 32); CPA_COMMIT();

    for (int kt = 0; kt < 64; kt++) {
        if (kt + 1 < 64) { CPA_WAIT1(); } else { CPA_WAIT0(); }
        __syncthreads();
        const int st = kt & 1;
        // convert fp32 stage -> bf16 hi/lo
        for (int idx = tid; idx < 1024; idx += 256) {
            int r = idx >> 3, cc = idx & 7;
            float4 w = *(const float4*)(sm + st*18432 + r*144 + cc*16);
            __nv_bfloat16 h0,h1,h2,h3,l0,l1,l2,l3;
            bsplit(w.x,h0,l0); bsplit(w.y,h1,l1); bsplit(w.z,h2,l2); bsplit(w.w,h3,l3);
            uint2 hp = { pk2(h0,h1), pk2(h2,h3) };
            uint2 lp = { pk2(l0,l1), pk2(l2,l3) };
            *(uint2*)(sm + 36864 + r*80 + cc*8) = hp;
            *(uint2*)(sm + 47104 + r*80 + cc*8) = lp;
        }
        __syncthreads();
        tile_compute<2>(aAH, aAL, aBH[st], aBL[st], wm, wn, lane, c);
        __syncthreads();
        if (kt + 2 < 64) { load_stage(st, (kt + 2) * 32); CPA_COMMIT(); }
    }

    const int g = lane >> 2, tg = lane & 3;
#pragma unroll
    for (int mi = 0; mi < 4; mi++)
#pragma unroll
        for (int ni = 0; ni < 2; ni++) {
            const int m = m0 + wm*64 + mi*16 + g;
            const int n = wn*16 + ni*8 + tg*2;
            const size_t base = ((size_t)(b*SS + m))*DIM + hd*DD + n;
            __nv_bfloat16 h0,h1,h2,h3,l0,l1,l2,l3;
            bsplit(c[mi][ni][0], h0, l0); bsplit(c[mi][ni][1], h1, l1);
            bsplit(c[mi][ni][2], h2, l2); bsplit(c[mi][ni][3], h3, l3);
            *(uint32_t*)&Ch[base]         = pk2(h0, h1);
            *(uint32_t*)&Cl[base]         = pk2(l0, l1);
            *(uint32_t*)&Ch[base + 8*DIM] = pk2(h2, h3);
            *(uint32_t*)&Cl[base + 8*DIM] = pk2(l2, l3);
        }
}

// ---- softmax fused with scale + bias + mask; in-place on attn ----
__global__ void softmax_kernel(float* __restrict__ attn,
                               const float* __restrict__ bias4d,
                               const float* __restrict__ pad)
{
    __shared__ float sred[8];
    const int tid = threadIdx.x;
    const int row = blockIdx.x;
    const int b = row >> 15, t = row & 2047;
    float* p = attn + (size_t)row * SS;
    const float* bp = bias4d + (size_t)row * SS;
    const float mt = 1.0f - pad[b * SS + t];

    float v[8];
    {
        float4 a0 = *(float4*)&p[tid*4],      q0 = *(const float4*)&bp[tid*4];
        float4 a1 = *(float4*)&p[1024+tid*4], q1 = *(const float4*)&bp[1024+tid*4];
        float4 m0 = *(const float4*)&pad[b*SS + tid*4];
        float4 m1 = *(const float4*)&pad[b*SS + 1024 + tid*4];
        v[0]=a0.x*0.125f+q0.x-1e9f*(1.f-mt*(1.f-m0.x));
        v[1]=a0.y*0.125f+q0.y-1e9f*(1.f-mt*(1.f-m0.y));
        v[2]=a0.z*0.125f+q0.z-1e9f*(1.f-mt*(1.f-m0.z));
        v[3]=a0.w*0.125f+q0.w-1e9f*(1.f-mt*(1.f-m0.w));
        v[4]=a1.x*0.125f+q1.x-1e9f*(1.f-mt*(1.f-m1.x));
        v[5]=a1.y*0.125f+q1.y-1e9f*(1.f-mt*(1.f-m1.y));
        v[6]=a1.z*0.125f+q1.z-1e9f*(1.f-mt*(1.f-m1.z));
        v[7]=a1.w*0.125f+q1.w-1e9f*(1.f-mt*(1.f-m1.w));
    }
    float m = v[0];
#pragma unroll
    for (int i = 1; i < 8; i++) m = fmaxf(m, v[i]);
#pragma unroll
    for (int o = 16; o; o >>= 1) m = fmaxf(m, __shfl_xor_sync(~0u, m, o));
    if ((tid & 31) == 0) sred[tid >> 5] = m;
    __syncthreads();
    if (tid == 0) { float x = sred[0];
#pragma unroll
        for (int i = 1; i < 8; i++) x = fmaxf(x, sred[i]); sred[0] = x; }
    __syncthreads();
    m = sred[0];
    __syncthreads();
    float s = 0.f;
#pragma unroll
    for (int i = 0; i < 8; i++) { v[i] = expf(v[i] - m); s += v[i]; }
#pragma unroll
    for (int o = 16; o; o >>= 1) s += __shfl_xor_sync(~0u, s, o);
    if ((tid & 31) == 0) sred[tid >> 5] = s;
    __syncthreads();
    if (tid == 0) { float x = 0.f;
#pragma unroll
        for (int i = 0; i < 8; i++) x += sred[i]; sred[0] = x; }
    __syncthreads();
    float inv = 1.0f / sred[0];
    float4 o0 = { v[0]*inv, v[1]*inv, v[2]*inv, v[3]*inv };
    float4 o1 = { v[4]*inv, v[5]*inv, v[6]*inv, v[7]*inv };
    *(float4*)&p[tid*4] = o0;
    *(float4*)&p[1024+tid*4] = o1;
}

// ---------------------------------------------------------------------------
extern "C" void kernel_launch(void* const* d_in, const int* in_sizes, int n_in,
                              void* d_out, int out_size)
{
    const float* xin[3] = { (const float*)d_in[0], (const float*)d_in[1], (const float*)d_in[2] };
    const float* attnbias = (const float*)d_in[3];
    const float* paddings = (const float*)d_in[4];
    const float* ww[4] = { (const float*)d_in[5], (const float*)d_in[7],
                           (const float*)d_in[9], (const float*)d_in[11] };
    const float* wb[4] = { (const float*)d_in[6], (const float*)d_in[8],
                           (const float*)d_in[10], (const float*)d_in[12] };

    float* out  = (float*)d_out;
    float* attn = out + (size_t)MT * DIM;

    __nv_bfloat16 *xh, *xl, *twh, *twl, *ph, *pl, *vth, *vtl, *ch, *cl;
    cudaGetSymbolAddress((void**)&xh, g_xh);   cudaGetSymbolAddress((void**)&xl, g_xl);
    cudaGetSymbolAddress((void**)&twh, g_twh); cudaGetSymbolAddress((void**)&twl, g_twl);
    cudaGetSymbolAddress((void**)&ph, g_ph);   cudaGetSymbolAddress((void**)&pl, g_pl);
    cudaGetSymbolAddress((void**)&vth, g_vth); cudaGetSymbolAddress((void**)&vtl, g_vtl);
    cudaGetSymbolAddress((void**)&ch, g_ch);   cudaGetSymbolAddress((void**)&cl, g_cl);

    static int attr_done = 0;
    if (!attr_done) {
        cudaFuncSetAttribute(gemm_pipe_kernel<0>, cudaFuncAttributeMaxDynamicSharedMemorySize, 81920);
        cudaFuncSetAttribute(gemm_pipe_kernel<1>, cudaFuncAttributeMaxDynamicSharedMemorySize, 81920);
        cudaFuncSetAttribute(gemm_pipe_kernel<2>, cudaFuncAttributeMaxDynamicSharedMemorySize, 81920);
        cudaFuncSetAttribute(av_pipe_kernel,      cudaFuncAttributeMaxDynamicSharedMemorySize, 77824);
        attr_done = 1;
    }

    const size_t NX = (size_t)MT * DIM;
    const size_t NW = (size_t)DIM * DIM;

    for (int i = 0; i < 3; i++)
        split_kernel<<<NX/1024, 256>>>(xin[i], xh + i*NX, xl + i*NX);
    for (int i = 0; i < 4; i++)
        wtrans_kernel<<<dim3(32,32), dim3(32,8)>>>(ww[i], twh + i*NW, twl + i*NW);

    // QKV projections, batched (z = 0,1,2)
    gemm_pipe_kernel<0><<<dim3(8,32,3), 256, 81920>>>(
        xh, xl, twh, twl, wb[0], wb[1], wb[2], nullptr, ph, pl);

    __nv_bfloat16 *qh = ph, *ql = pl;
    __nv_bfloat16 *kh = ph + NX, *kl = pl + NX;
    __nv_bfloat16 *vh = ph + 2*NX, *vl = pl + 2*NX;

    vtrans_kernel<<<dim3(32, NBH), 256>>>(vh, vth);
    vtrans_kernel<<<dim3(32, NBH), 256>>>(vl, vtl);

    // raw logits -> attn
    gemm_pipe_kernel<2><<<dim3(16,16,NBH), 256, 81920>>>(
        qh, ql, kh, kl, nullptr, nullptr, nullptr, attn, nullptr, nullptr);

    // softmax (scale+bias+mask fused), in-place
    softmax_kernel<<<NBH*SS, 256>>>(attn, attnbias, paddings);

    // AV -> concat split
    av_pipe_kernel<<<dim3(16, NBH), 256, 77824>>>(attn, vth, vtl, ch, cl);

    // output projection -> fp32 out
    gemm_pipe_kernel<1><<<dim3(8,32), 256, 81920>>>(
        ch, cl, twh + 3*NW, twl + 3*NW, wb[3], nullptr, nullptr, out, nullptr, nullptr);
}

// round 7
// speedup vs baseline: 2.2631x; 1.0125x over previous
#include <cuda_runtime.h>
#include <cuda_bf16.h>
#include <stdint.h>

#define BB  2
#define SS  2048
#define DIM 1024
#define HH  16
#define DD  64
#define MT  (BB*SS)
#define NBH (BB*HH)

// ---- device scratch ----
__device__ __nv_bfloat16 g_xh[3][MT*DIM], g_xl[3][MT*DIM];
__device__ __nv_bfloat16 g_twh[4][DIM*DIM], g_twl[4][DIM*DIM];
__device__ __nv_bfloat16 g_ph[3][NBH*SS*DD], g_pl[3][NBH*SS*DD];
__device__ __nv_bfloat16 g_vth[NBH*DD*SS], g_vtl[NBH*DD*SS];
__device__ __nv_bfloat16 g_ch[MT*DIM], g_cl[MT*DIM];
__device__ float2 g_part[(size_t)NBH*SS*16];   // per (row, stile) partial (max, sumexp)
__device__ float2 g_ms[(size_t)NBH*SS];        // per row (max, 1/sum)

#define STRD 40

// ---- helpers ----
__device__ __forceinline__ uint32_t s2u(const void* p){
    uint32_t a;
    asm("{ .reg .u64 t; cvta.to.shared.u64 t, %1; cvt.u32.u64 %0, t; }":"=r"(a):"l"(p));
    return a;
}
__device__ __forceinline__ void bsplit(float v, __nv_bfloat16& h, __nv_bfloat16& l){
    h = __float2bfloat16(v);
    l = __float2bfloat16(v - __bfloat162float(h));
}
__device__ __forceinline__ uint32_t pk2(__nv_bfloat16 a, __nv_bfloat16 b){
    __nv_bfloat162 t(a, b); return *(uint32_t*)&t;
}
__device__ __forceinline__ void ldmx4(uint32_t* r, uint32_t addr){
    asm volatile("ldmatrix.sync.aligned.m8n8.x4.shared.b16 {%0,%1,%2,%3}, [%4];"
        : "=r"(r[0]),"=r"(r[1]),"=r"(r[2]),"=r"(r[3]) : "r"(addr));
}
__device__ __forceinline__ void ldmx2(uint32_t* r, uint32_t addr){
    asm volatile("ldmatrix.sync.aligned.m8n8.x2.shared.b16 {%0,%1}, [%2];"
        : "=r"(r[0]),"=r"(r[1]) : "r"(addr));
}
__device__ __forceinline__ void mma16816(float* c, const uint32_t* a, const uint32_t* b){
    asm volatile("mma.sync.aligned.m16n8k16.row.col.f32.bf16.bf16.f32 "
        "{%0,%1,%2,%3}, {%4,%5,%6,%7}, {%8,%9}, {%0,%1,%2,%3};"
        : "+f"(c[0]),"+f"(c[1]),"+f"(c[2]),"+f"(c[3])
        : "r"(a[0]),"r"(a[1]),"r"(a[2]),"r"(a[3]), "r"(b[0]),"r"(b[1]));
}
__device__ __forceinline__ void cpa16(uint32_t s, const void* g){
    asm volatile("cp.async.cg.shared.global [%0], [%1], 16;" :: "r"(s), "l"(g));
}
#define CPA_COMMIT() asm volatile("cp.async.commit_group;" ::: "memory")
#define CPA_WAIT1()  asm volatile("cp.async.wait_group 1;" ::: "memory")
#define CPA_WAIT0()  asm volatile("cp.async.wait_group 0;" ::: "memory")

// ---- warp-tile compute ----
template<int WNT>
__device__ __forceinline__ void tile_compute(
    uint32_t aAh, uint32_t aAl, uint32_t aBh, uint32_t aBl,
    int wm, int wn, int lane, float c[4][WNT][4])
{
#pragma unroll
    for (int h = 0; h < 2; h++) {
        uint32_t fAh[4][4], fAl[4][4], fBh[WNT][2], fBl[WNT][2];
        const int ar = wm*64 + (lane & 15);
        const int ac = h*16 + ((lane >> 4) << 3);
#pragma unroll
        for (int mi = 0; mi < 4; mi++) {
            uint32_t off = (uint32_t)((ar + mi*16)*STRD + ac) * 2;
            ldmx4(fAh[mi], aAh + off);
            ldmx4(fAl[mi], aAl + off);
        }
        const int br = wn*(WNT*8) + (lane & 7);
        const int bc = h*16 + ((lane >> 3) & 1)*8;
#pragma unroll
        for (int ni = 0; ni < WNT; ni++) {
            uint32_t off = (uint32_t)((br + ni*8)*STRD + bc) * 2;
            ldmx2(fBh[ni], aBh + off);
            ldmx2(fBl[ni], aBl + off);
        }
#pragma unroll
        for (int mi = 0; mi < 4; mi++)
#pragma unroll
            for (int ni = 0; ni < WNT; ni++) {
                mma16816(c[mi][ni], fAh[mi], fBh[ni]);
                mma16816(c[mi][ni], fAh[mi], fBl[ni]);
                mma16816(c[mi][ni], fAl[mi], fBh[ni]);
            }
    }
}

// ---- fp32 -> bf16 hi/lo split ----
__global__ void split_kernel(const float* __restrict__ x,
                             __nv_bfloat16* __restrict__ h,
                             __nv_bfloat16* __restrict__ l)
{
    int i = (blockIdx.x * blockDim.x + threadIdx.x) * 4;
    float4 v = *(const float4*)&x[i];
    __nv_bfloat16 h0,h1,h2,h3,l0,l1,l2,l3;
    bsplit(v.x,h0,l0); bsplit(v.y,h1,l1); bsplit(v.z,h2,l2); bsplit(v.w,h3,l3);
    uint2 hp = { pk2(h0,h1), pk2(h2,h3) };
    uint2 lp = { pk2(l0,l1), pk2(l2,l3) };
    *(uint2*)&h[i] = hp; *(uint2*)&l[i] = lp;
}

// ---- W[K,N] -> WT[N,K] hi/lo ----
__global__ void wtrans_kernel(const float* __restrict__ W,
                              __nv_bfloat16* __restrict__ Th,
                              __nv_bfloat16* __restrict__ Tl)
{
    __shared__ float t[32][33];
    int bx = blockIdx.x * 32, by = blockIdx.y * 32;
    int x = threadIdx.x, y = threadIdx.y;
    for (int yy = y; yy < 32; yy += 8)
        t[yy][x] = W[(size_t)(by + yy) * DIM + bx + x];
    __syncthreads();
    for (int yy = y; yy < 32; yy += 8) {
        __nv_bfloat16 h, l; bsplit(t[x][yy], h, l);
        Th[(size_t)(bx + yy) * DIM + by + x] = h;
        Tl[(size_t)(bx + yy) * DIM + by + x] = l;
    }
}

// ---- V [bh,s,d] -> VT [bh,d,s] (bf16) ----
__global__ void vtrans_kernel(const __nv_bfloat16* __restrict__ V,
                              __nv_bfloat16* __restrict__ VT)
{
    __shared__ __nv_bfloat16 t[64][65];
    int bh = blockIdx.y, s0 = blockIdx.x * 64;
    int tid = threadIdx.x;
    for (int i = tid; i < 64*64; i += 256) {
        int r = i >> 6, c = i & 63;
        t[r][c] = V[((size_t)bh * SS + s0 + r) * DD + c];
    }
    __syncthreads();
    for (int i = tid; i < 64*64; i += 256) {
        int r = i >> 6, c = i & 63;
        VT[((size_t)bh * DD + r) * SS + s0 + c] = t[c][r];
    }
}

// ===========================================================================
// Projection GEMMs (cp.async 2-stage): MODE 0 QKV -> split-head (+bias),
// MODE 1 out-proj -> fp32 (+bias). dyn smem 81920.
// ===========================================================================
template<int MODE>
__global__ __launch_bounds__(256) void gemm_pipe_kernel(
    const __nv_bfloat16* __restrict__ Ah_, const __nv_bfloat16* __restrict__ Al_,
    const __nv_bfloat16* __restrict__ Bh_, const __nv_bfloat16* __restrict__ Bl_,
    const float* __restrict__ b0, const float* __restrict__ b1, const float* __restrict__ b2,
    float* __restrict__ outF,
    __nv_bfloat16* __restrict__ Oh_, __nv_bfloat16* __restrict__ Ol_)
{
    constexpr int NT = 32;
    extern __shared__ char sm[];
    const uint32_t sb = s2u(sm);
    const uint32_t aAH[2] = { sb,          sb + 10240 };
    const uint32_t aAL[2] = { sb + 20480,  sb + 30720 };
    const uint32_t aBH[2] = { sb + 40960,  sb + 51200 };
    const uint32_t aBL[2] = { sb + 61440,  sb + 71680 };

    const int tid = threadIdx.x, lane = tid & 31, wid = tid >> 5;
    const int wm = wid >> 2, wn = wid & 3;
    const size_t NX = (size_t)MT * DIM, NW = (size_t)DIM * DIM;

    const int z  = (MODE == 0) ? blockIdx.z : 0;
    const int n0 = blockIdx.x*128, m0 = blockIdx.y*128;

    const __nv_bfloat16* Abh = (MODE == 0 ? Ah_ + z*NX : Ah_) + (size_t)m0 * DIM;
    const __nv_bfloat16* Abl = (MODE == 0 ? Al_ + z*NX : Al_) + (size_t)m0 * DIM;
    const __nv_bfloat16* Bbh = (MODE == 0 ? Bh_ + z*NW : Bh_) + (size_t)n0 * DIM;
    const __nv_bfloat16* Bbl = (MODE == 0 ? Bl_ + z*NW : Bl_) + (size_t)n0 * DIM;
    const float* bias = (MODE == 0) ? (z == 0 ? b0 : (z == 1 ? b1 : b2)) : b0;

    float c[4][4][4] = {};

    auto load_stage = [&](int st, int k0){
        for (int idx = tid; idx < 512; idx += 256) {
            int r = idx >> 2, cc = idx & 3;
            uint32_t so = (uint32_t)r*80 + cc*16;
            size_t go = (size_t)r*DIM + k0 + cc*8;
            cpa16(aAH[st] + so, Abh + go);
            cpa16(aAL[st] + so, Abl + go);
            cpa16(aBH[st] + so, Bbh + go);
            cpa16(aBL[st] + so, Bbl + go);
        }
    };

    load_stage(0, 0);  CPA_COMMIT();
    load_stage(1, 32); CPA_COMMIT();

    for (int kt = 0; kt < NT; kt++) {
        if (kt + 1 < NT) { CPA_WAIT1(); } else { CPA_WAIT0(); }
        __syncthreads();
        const int st = kt & 1;
        tile_compute<4>(aAH[st], aAL[st], aBH[st], aBL[st], wm, wn, lane, c);
        __syncthreads();
        if (kt + 2 < NT) { load_stage(st, (kt + 2) * 32); CPA_COMMIT(); }
    }

    const int g = lane >> 2, tg = lane & 3;
#pragma unroll
    for (int mi = 0; mi < 4; mi++)
#pragma unroll
        for (int ni = 0; ni < 4; ni++) {
            const int m = m0 + wm*64 + mi*16 + g;
            const int n = n0 + wn*32 + ni*8 + tg*2;
            const float v00 = c[mi][ni][0], v01 = c[mi][ni][1];
            const float v10 = c[mi][ni][2], v11 = c[mi][ni][3];
            const float q0 = bias[n], q1 = bias[n+1];
            if (MODE == 1) {
                float2 r0 = { v00 + q0, v01 + q1 };
                float2 r1 = { v10 + q0, v11 + q1 };
                *(float2*)&outF[(size_t)m*DIM + n]     = r0;
                *(float2*)&outF[(size_t)(m+8)*DIM + n] = r1;
            } else {
                const int b = m >> 11, hd = n >> 6, d = n & 63;
                const size_t base = z*NX + (((size_t)(b*HH + hd))*SS + (m & 2047))*DD + d;
                __nv_bfloat16 h0,h1,h2,h3,l0,l1,l2,l3;
                bsplit(v00 + q0, h0, l0); bsplit(v01 + q1, h1, l1);
                bsplit(v10 + q0, h2, l2); bsplit(v11 + q1, h3, l3);
                *(uint32_t*)&Oh_[base]        = pk2(h0, h1);
                *(uint32_t*)&Ol_[base]        = pk2(l0, l1);
                *(uint32_t*)&Oh_[base + 8*DD] = pk2(h2, h3);
                *(uint32_t*)&Ol_[base + 8*DD] = pk2(l2, l3);
            }
        }
}

// ===========================================================================
// Logits fused: QK^T, scale+bias+mask in epilogue, write biased logits,
// emit per-(row, stile) (max, sumexp) partials. grid (16,16,32). dyn 81920.
// ===========================================================================
__global__ __launch_bounds__(256) void logits_fused_kernel(
    const __nv_bfloat16* __restrict__ Qh, const __nv_bfloat16* __restrict__ Ql,
    const __nv_bfloat16* __restrict__ Kh, const __nv_bfloat16* __restrict__ Kl,
    const float* __restrict__ bias4d, const float* __restrict__ pad,
    float* __restrict__ attn, float2* __restrict__ part)
{
    extern __shared__ char sm[];
    const uint32_t sb = s2u(sm);
    const uint32_t aAH[2] = { sb,          sb + 10240 };
    const uint32_t aAL[2] = { sb + 20480,  sb + 30720 };
    const uint32_t aBH[2] = { sb + 40960,  sb + 51200 };
    const uint32_t aBL[2] = { sb + 61440,  sb + 71680 };

    const int tid = threadIdx.x, lane = tid & 31, wid = tid >> 5;
    const int wm = wid >> 2, wn = wid & 3;
    const int bh = blockIdx.z, b = bh >> 4;
    const int stile = blockIdx.x;
    const int n0 = stile*128, m0 = blockIdx.y*128;

    const __nv_bfloat16* Abh = Qh + ((size_t)bh*SS + m0) * DD;
    const __nv_bfloat16* Abl = Ql + ((size_t)bh*SS + m0) * DD;
    const __nv_bfloat16* Bbh = Kh + ((size_t)bh*SS + n0) * DD;
    const __nv_bfloat16* Bbl = Kl + ((size_t)bh*SS + n0) * DD;

    float c[4][4][4] = {};

    auto load_stage = [&](int st, int k0){
        for (int idx = tid; idx < 512; idx += 256) {
            int r = idx >> 2, cc = idx & 3;
            uint32_t so = (uint32_t)r*80 + cc*16;
            size_t go = (size_t)r*DD + k0 + cc*8;
            cpa16(aAH[st] + so, Abh + go);
            cpa16(aAL[st] + so, Abl + go);
            cpa16(aBH[st] + so, Bbh + go);
            cpa16(aBL[st] + so, Bbl + go);
        }
    };

    load_stage(0, 0);  CPA_COMMIT();
    load_stage(1, 32); CPA_COMMIT();

    for (int kt = 0; kt < 2; kt++) {
        if (kt == 0) { CPA_WAIT1(); } else { CPA_WAIT0(); }
        __syncthreads();
        const int st = kt;
        tile_compute<4>(aAH[st], aAL[st], aBH[st], aBL[st], wm, wn, lane, c);
        __syncthreads();
    }

    // epilogue: bias+mask, write logits, per-row partial (max,sumexp)
    float2* spair = (float2*)sm;   // [4][128]
    const int g = lane >> 2, tg = lane & 3;

#pragma unroll
    for (int mi = 0; mi < 4; mi++)
#pragma unroll
        for (int half = 0; half < 2; half++) {
            const int rloc = wm*64 + mi*16 + half*8 + g;
            const int t = m0 + rloc;
            const float mt = 1.0f - pad[b*SS + t];
            const float* bp = &bias4d[((size_t)bh*SS + t)*SS + n0];
            float* ap = &attn[((size_t)bh*SS + t)*SS + n0];
            float vv[8];
#pragma unroll
            for (int ni = 0; ni < 4; ni++) {
                const int nl = wn*32 + ni*8 + tg*2;
                const float ms0 = 1.0f - pad[b*SS + n0 + nl];
                const float ms1 = 1.0f - pad[b*SS + n0 + nl + 1];
                float x0 = c[mi][ni][half*2+0]*0.125f + bp[nl]   - 1e9f*(1.0f - mt*ms0);
                float x1 = c[mi][ni][half*2+1]*0.125f + bp[nl+1] - 1e9f*(1.0f - mt*ms1);
                vv[ni*2]   = x0;
                vv[ni*2+1] = x1;
                float2 w = { x0, x1 };
                *(float2*)&ap[nl] = w;
            }
            float mx = vv[0];
#pragma unroll
            for (int j = 1; j < 8; j++) mx = fmaxf(mx, vv[j]);
            mx = fmaxf(mx, __shfl_xor_sync(~0u, mx, 1));
            mx = fmaxf(mx, __shfl_xor_sync(~0u, mx, 2));
            float se = 0.f;
#pragma unroll
            for (int j = 0; j < 8; j++) se += __expf(vv[j] - mx);
            se += __shfl_xor_sync(~0u, se, 1);
            se += __shfl_xor_sync(~0u, se, 2);
            if (tg == 0) spair[wn*128 + rloc] = make_float2(mx, se);
        }
    __syncthreads();

    if (tid < 128) {
        float2 p0 = spair[tid], p1 = spair[128 + tid];
        float2 p2 = spair[256 + tid], p3 = spair[384 + tid];
        float m01 = fmaxf(p0.x, p1.x), m23 = fmaxf(p2.x, p3.x);
        float m = fmaxf(m01, m23);
        float s = p0.y*__expf(p0.x - m) + p1.y*__expf(p1.x - m)
                + p2.y*__expf(p2.x - m) + p3.y*__expf(p3.x - m);
        part[(((size_t)bh*SS) + m0 + tid)*16 + stile] = make_float2(m, s);
    }
}

// ---- merge 16 partials per row -> (max, 1/sum) ----
__global__ void ms_reduce_kernel(const float2* __restrict__ part,
                                 float2* __restrict__ ms)
{
    const int row = blockIdx.x * 256 + threadIdx.x;
    const float2* p = part + (size_t)row * 16;
    float2 v[16];
#pragma unroll
    for (int i = 0; i < 4; i++) {
        float4 a = *(const float4*)&p[i*2];
        float4 b2 = *(const float4*)&p[i*2 + 8];
        v[i*2+0] = make_float2(a.x, a.y);  v[i*2+1] = make_float2(a.z, a.w);
        v[i*2+8] = make_float2(b2.x, b2.y); v[i*2+9] = make_float2(b2.z, b2.w);
    }
    float m = v[0].x;
#pragma unroll
    for (int i = 1; i < 16; i++) m = fmaxf(m, v[i].x);
    float s = 0.f;
#pragma unroll
    for (int i = 0; i < 16; i++) s += v[i].y * __expf(v[i].x - m);
    ms[row] = make_float2(m, 1.0f / s);
}

// ===========================================================================
// AV fused: read biased logits, w = exp(x-m)*invS, write final weights,
// split to bf16 hi/lo in smem, MMA with VT. grid (16,32). dyn 78848.
// ===========================================================================
__global__ __launch_bounds__(256) void av_pipe_kernel(
    float* __restrict__ attn,          // in: biased logits, out: weights
    const float2* __restrict__ ms,
    const __nv_bfloat16* __restrict__ VTh, const __nv_bfloat16* __restrict__ VTl,
    __nv_bfloat16* __restrict__ Ch, __nv_bfloat16* __restrict__ Cl)
{
    extern __shared__ char sm[];
    const uint32_t sb = s2u(sm);
    const uint32_t aAF[2] = { sb, sb + 18432 };
    const uint32_t aAH = sb + 36864, aAL = sb + 47104;
    const uint32_t aBH[2] = { sb + 57344, sb + 62464 };
    const uint32_t aBL[2] = { sb + 67584, sb + 72704 };
    float2* sms = (float2*)(sm + 77824);   // [128]

    const int tid = threadIdx.x, lane = tid & 31, wid = tid >> 5;
    const int wm = wid >> 2, wn = wid & 3;
    const int bh = blockIdx.y, b = bh >> 4, hd = bh & 15;
    const int m0 = blockIdx.x * 128;

    float* Abf = attn + ((size_t)bh*SS + m0) * SS;
    const __nv_bfloat16* Bbh = VTh + (size_t)bh*DD*SS;
    const __nv_bfloat16* Bbl = VTl + (size_t)bh*DD*SS;

    if (tid < 128) sms[tid] = ms[(size_t)bh*SS + m0 + tid];

    float c[4][2][4] = {};

    auto load_stage = [&](int st, int k0){
        for (int idx = tid; idx < 1024; idx += 256) {
            int r = idx >> 3, cc = idx & 7;
            cpa16(aAF[st] + (uint32_t)r*144 + cc*16, Abf + (size_t)r*SS + k0 + cc*4);
        }
        for (int idx = tid; idx < 256; idx += 256) {
            int r = idx >> 2, cc = idx & 3;
            uint32_t so = (uint32_t)r*80 + cc*16;
            size_t go = (size_t)r*SS + k0 + cc*8;
            cpa16(aBH[st] + so, Bbh + go);
            cpa16(aBL[st] + so, Bbl + go);
        }
    };

    load_stage(0, 0);  CPA_COMMIT();
    load_stage(1, 32); CPA_COMMIT();

    for (int kt = 0; kt < 64; kt++) {
        if (kt + 1 < 64) { CPA_WAIT1(); } else { CPA_WAIT0(); }
        __syncthreads();
        const int st = kt & 1;
        const int k0 = kt * 32;
        // convert: exp-normalize, write weights to gmem, split to bf16 smem
        for (int idx = tid; idx < 1024; idx += 256) {
            int r = idx >> 3, cc = idx & 7;
            float4 w = *(const float4*)(sm + st*18432 + r*144 + cc*16);
            float2 q = sms[r];
            w.x = __expf(w.x - q.x) * q.y;
            w.y = __expf(w.y - q.x) * q.y;
            w.z = __expf(w.z - q.x) * q.y;
            w.w = __expf(w.w - q.x) * q.y;
            *(float4*)&Abf[(size_t)r*SS + k0 + cc*4] = w;
            __nv_bfloat16 h0,h1,h2,h3,l0,l1,l2,l3;
            bsplit(w.x,h0,l0); bsplit(w.y,h1,l1); bsplit(w.z,h2,l2); bsplit(w.w,h3,l3);
            uint2 hp = { pk2(h0,h1), pk2(h2,h3) };
            uint2 lp = { pk2(l0,l1), pk2(l2,l3) };
            *(uint2*)(sm + 36864 + r*80 + cc*8) = hp;
            *(uint2*)(sm + 47104 + r*80 + cc*8) = lp;
        }
        __syncthreads();
        tile_compute<2>(aAH, aAL, aBH[st], aBL[st], wm, wn, lane, c);
        __syncthreads();
        if (kt + 2 < 64) { load_stage(st, (kt + 2) * 32); CPA_COMMIT(); }
    }

    const int g = lane >> 2, tg = lane & 3;
#pragma unroll
    for (int mi = 0; mi < 4; mi++)
#pragma unroll
        for (int ni = 0; ni < 2; ni++) {
            const int m = m0 + wm*64 + mi*16 + g;
            const int n = wn*16 + ni*8 + tg*2;
            const size_t base = ((size_t)(b*SS + m))*DIM + hd*DD + n;
            __nv_bfloat16 h0,h1,h2,h3,l0,l1,l2,l3;
            bsplit(c[mi][ni][0], h0, l0); bsplit(c[mi][ni][1], h1, l1);
            bsplit(c[mi][ni][2], h2, l2); bsplit(c[mi][ni][3], h3, l3);
            *(uint32_t*)&Ch[base]         = pk2(h0, h1);
            *(uint32_t*)&Cl[base]         = pk2(l0, l1);
            *(uint32_t*)&Ch[base + 8*DIM] = pk2(h2, h3);
            *(uint32_t*)&Cl[base + 8*DIM] = pk2(l2, l3);
        }
}

// ---------------------------------------------------------------------------
extern "C" void kernel_launch(void* const* d_in, const int* in_sizes, int n_in,
                              void* d_out, int out_size)
{
    const float* xin[3] = { (const float*)d_in[0], (const float*)d_in[1], (const float*)d_in[2] };
    const float* attnbias = (const float*)d_in[3];
    const float* paddings = (const float*)d_in[4];
    const float* ww[4] = { (const float*)d_in[5], (const float*)d_in[7],
                           (const float*)d_in[9], (const float*)d_in[11] };
    const float* wb[4] = { (const float*)d_in[6], (const float*)d_in[8],
                           (const float*)d_in[10], (const float*)d_in[12] };

    float* out  = (float*)d_out;
    float* attn = out + (size_t)MT * DIM;

    __nv_bfloat16 *xh, *xl, *twh, *twl, *ph, *pl, *vth, *vtl, *ch, *cl;
    float2 *partp, *msp;
    cudaGetSymbolAddress((void**)&xh, g_xh);   cudaGetSymbolAddress((void**)&xl, g_xl);
    cudaGetSymbolAddress((void**)&twh, g_twh); cudaGetSymbolAddress((void**)&twl, g_twl);
    cudaGetSymbolAddress((void**)&ph, g_ph);   cudaGetSymbolAddress((void**)&pl, g_pl);
    cudaGetSymbolAddress((void**)&vth, g_vth); cudaGetSymbolAddress((void**)&vtl, g_vtl);
    cudaGetSymbolAddress((void**)&ch, g_ch);   cudaGetSymbolAddress((void**)&cl, g_cl);
    cudaGetSymbolAddress((void**)&partp, g_part); cudaGetSymbolAddress((void**)&msp, g_ms);

    static int attr_done = 0;
    if (!attr_done) {
        cudaFuncSetAttribute(gemm_pipe_kernel<0>,  cudaFuncAttributeMaxDynamicSharedMemorySize, 81920);
        cudaFuncSetAttribute(gemm_pipe_kernel<1>,  cudaFuncAttributeMaxDynamicSharedMemorySize, 81920);
        cudaFuncSetAttribute(logits_fused_kernel,  cudaFuncAttributeMaxDynamicSharedMemorySize, 81920);
        cudaFuncSetAttribute(av_pipe_kernel,       cudaFuncAttributeMaxDynamicSharedMemorySize, 78848);
        attr_done = 1;
    }

    const size_t NX = (size_t)MT * DIM;
    const size_t NW = (size_t)DIM * DIM;

    for (int i = 0; i < 3; i++)
        split_kernel<<<NX/1024, 256>>>(xin[i], xh + i*NX, xl + i*NX);
    for (int i = 0; i < 4; i++)
        wtrans_kernel<<<dim3(32,32), dim3(32,8)>>>(ww[i], twh + i*NW, twl + i*NW);

    // QKV projections, batched
    gemm_pipe_kernel<0><<<dim3(8,32,3), 256, 81920>>>(
        xh, xl, twh, twl, wb[0], wb[1], wb[2], nullptr, ph, pl);

    __nv_bfloat16 *qh = ph, *ql = pl;
    __nv_bfloat16 *kh = ph + NX, *kl = pl + NX;
    __nv_bfloat16 *vh = ph + 2*NX, *vl = pl + 2*NX;

    vtrans_kernel<<<dim3(32, NBH), 256>>>(vh, vth);
    vtrans_kernel<<<dim3(32, NBH), 256>>>(vl, vtl);

    // logits + bias + mask + softmax partials
    logits_fused_kernel<<<dim3(16,16,NBH), 256, 81920>>>(
        qh, ql, kh, kl, attnbias, paddings, attn, partp);

    // merge partials -> (max, 1/sum) per row
    ms_reduce_kernel<<<(NBH*SS)/256, 256>>>(partp, msp);

    // AV: normalize + write weights + MMA
    av_pipe_kernel<<<dim3(16, NBH), 256, 78848>>>(attn, msp, vth, vtl, ch, cl);

    // output projection -> fp32 out
    gemm_pipe_kernel<1><<<dim3(8,32), 256, 81920>>>(
        ch, cl, twh + 3*NW, twl + 3*NW, wb[3], nullptr, nullptr, out, nullptr, nullptr);
}